// round 14
// baseline (speedup 1.0000x reference)
#include <cuda_runtime.h>
#include <cuda_fp16.h>
#include <math.h>
#include <stdint.h>

#define B_ 32
#define N_ 256
#define D_ 512
#define H_ 8
#define DH_ 64
#define F_ 2048
#define L_ 8
#define LC_ 2
#define NTOK_ 257
#define QKVW_ 1536
#define KVW_ 1024

// ---------------- scratch (device globals; no allocation allowed) ----------------
static __device__ float  g_h  [B_*N_*D_];
static __device__ __half g_hn [B_*N_*D_];
static __device__ __half g_qkv[B_*N_*QKVW_];
static __device__ __half g_ao [B_*N_*D_];
static __device__ float  g_interT[B_*H_*N_*N_];
static __device__ __half g_t  [B_*N_*F_];
static __device__ __half g_cn [B_*NTOK_*D_];
static __device__ float  g_khvh[B_*NTOK_*KVW_];
static __device__ float  g_qh [B_*D_];
static __device__ __half g_co [B_*D_];
static __device__ float  g_query[B_*D_];
static __device__ __half g_queryh[B_*D_];
static __device__ __half g_cfn[B_*D_];
static __device__ __half g_cff[B_*F_];
static __device__ float  g_ckvb[LC_*KVW_];
static __device__ int    g_mask_mode;

// transposed fp16 weights: [N][K] row-major
static __device__ __half g_wqkvT[L_*QKVW_*D_];
static __device__ __half g_woT [L_*D_*D_];
static __device__ __half g_w1T [L_*F_*D_];
static __device__ __half g_w2T [L_*D_*F_];
static __device__ __half g_cqkT[LC_*D_*D_];
static __device__ __half g_ckvT[LC_*KVW_*D_];
static __device__ __half g_cokT[LC_*D_*D_];
static __device__ __half g_cw1T[LC_*F_*D_];
static __device__ __half g_cw2T[LC_*D_*F_];

// ---------------- mask dtype detection ----------------
__global__ void detect_mask_kernel(const unsigned int* m) {
    unsigned int w = m[0];
    int mode = 0;
    if (w == 0x01010101u) mode = 1;
    else if (w == 0x3F800000u) mode = 2;
    g_mask_mode = mode;
}

__device__ __forceinline__ bool mget(const void* m, int idx) {
    int mode = g_mask_mode;
    if (mode == 1) return ((const unsigned char*)m)[idx] != 0;
    if (mode == 2) return ((const float*)m)[idx] != 0.0f;
    return ((const int*)m)[idx] != 0;
}

// ---------------- tiny utility kernels ----------------
__global__ void copy_kernel(const float* __restrict__ src, float* __restrict__ dst, int n) {
    int i = blockIdx.x * 256 + threadIdx.x;
    if (i < n) dst[i] = src[i];
}

__global__ void f2h_kernel(const float* __restrict__ src, __half* __restrict__ dst, int n) {
    int i = blockIdx.x * 256 + threadIdx.x;
    if (i < n) dst[i] = __float2half(src[i]);
}

__global__ void bcast_token_kernel(const float* __restrict__ tok) {
    int i = blockIdx.x * 256 + threadIdx.x;
    if (i < B_*D_) g_query[i] = tok[i % D_];
}

// combined class K/V bias
__global__ void ckvb_kernel(const float* __restrict__ kb, const float* __restrict__ vb) {
    int i = blockIdx.x * 256 + threadIdx.x;
    if (i >= LC_ * KVW_) return;
    int l = i >> 10, c = i & 1023;
    g_ckvb[i] = (c < 512) ? kb[l * 512 + c] : vb[l * 512 + c - 512];
}

// inter [B,N,N,H] -> interT [B,H,N,N]
__global__ void transpose_inter(const float* __restrict__ inter, float* __restrict__ interT) {
    int row = blockIdx.x;
    int b = row >> 8, qi = row & 255;
    int k = threadIdx.x;
    const float4* ip = (const float4*)(inter + ((long)row * N_ + k) * H_);
    float4 i0 = ip[0], i1 = ip[1];
    float v[8] = {i0.x, i0.y, i0.z, i0.w, i1.x, i1.y, i1.z, i1.w};
    #pragma unroll
    for (int h = 0; h < H_; h++)
        interT[((long)(b * H_ + h) * N_ + qi) * N_ + k] = v[h];
}

// ---------------- all weight transposes in ONE launch (64x64 tiles) ----------------
#define NWT 11
struct WTable {
    const float* src[NWT];
    __half*      dst[NWT];
    int          K[NWT], N[NWT];
    long         sS[NWT], dS[NWT];
    int          base[NWT + 1];
};

__global__ void transpose_all(WTable w) {
    __shared__ float tile[64][65];
    int bx = blockIdx.x;
    int gsel = 0;
    #pragma unroll
    for (int i = 1; i < NWT; i++) if (bx >= w.base[i]) gsel = i;
    int local = bx - w.base[gsel];
    int K = w.K[gsel], N = w.N[gsel];
    int ncols = N >> 6;
    int tpl = (K >> 6) * ncols;
    int layer = local / tpl;
    int rem = local % tpl;
    int k0 = (rem / ncols) * 64, n0 = (rem % ncols) * 64;
    const float* src = w.src[gsel] + (long)layer * w.sS[gsel];
    __half* dst = w.dst[gsel] + (long)layer * w.dS[gsel];
    int t = threadIdx.y * 32 + threadIdx.x;
    #pragma unroll
    for (int i = 0; i < 4; i++) {
        int r = i * 16 + (t >> 4);
        int c = (t & 15) * 4;
        float4 v = *(const float4*)(src + (long)(k0 + r) * N + n0 + c);
        tile[r][c] = v.x; tile[r][c + 1] = v.y; tile[r][c + 2] = v.z; tile[r][c + 3] = v.w;
    }
    __syncthreads();
    #pragma unroll
    for (int i = 0; i < 8; i++) {
        int n = i * 8 + (t >> 5);
        int kc = (t & 31) * 2;
        __half2 hv = __floats2half2_rn(tile[kc][n], tile[kc + 1][n]);
        *(__half2*)(dst + (long)(n0 + n) * K + k0 + kc) = hv;
    }
}

// ---------------- LayerNorm (eps = 1e-3): one WARP per row, MLP=4 ----------------
__device__ __forceinline__ void ln_row_warp(const float* __restrict__ x, __half* __restrict__ o,
                                            const float* __restrict__ g, const float* __restrict__ bb) {
    int lane = threadIdx.x & 31;
    float4 v[4];
    #pragma unroll
    for (int i = 0; i < 4; i++)
        v[i] = *(const float4*)(x + (i * 32 + lane) * 4);
    float s = 0.f, s2 = 0.f;
    #pragma unroll
    for (int i = 0; i < 4; i++) {
        s  += v[i].x + v[i].y + v[i].z + v[i].w;
        s2 += v[i].x*v[i].x + v[i].y*v[i].y + v[i].z*v[i].z + v[i].w*v[i].w;
    }
    #pragma unroll
    for (int off = 16; off; off >>= 1) {
        s  += __shfl_xor_sync(0xffffffffu, s,  off);
        s2 += __shfl_xor_sync(0xffffffffu, s2, off);
    }
    float mean = s * (1.f / D_);
    float var  = s2 * (1.f / D_) - mean * mean;
    float r = rsqrtf(var + 1e-3f);
    #pragma unroll
    for (int i = 0; i < 4; i++) {
        int idx = (i * 32 + lane) * 4;
        float4 g4 = *(const float4*)(g + idx);
        float4 b4 = *(const float4*)(bb + idx);
        float o0 = (v[i].x - mean) * r * g4.x + b4.x;
        float o1 = (v[i].y - mean) * r * g4.y + b4.y;
        float o2 = (v[i].z - mean) * r * g4.z + b4.z;
        float o3 = (v[i].w - mean) * r * g4.w + b4.w;
        __half2 h0 = __floats2half2_rn(o0, o1);
        __half2 h1 = __floats2half2_rn(o2, o3);
        uint2 u; u.x = *(unsigned*)&h0; u.y = *(unsigned*)&h1;
        *(uint2*)(o + idx) = u;
    }
}

// 8 rows per 256-thread block
__global__ void ln_kernel(const float* __restrict__ in, __half* __restrict__ out,
                          const float* __restrict__ g, const float* __restrict__ b) {
    long row = blockIdx.x * 8 + (threadIdx.x >> 5);
    ln_row_warp(in + row * D_, out + row * D_, g, b);
}

__global__ void ln_cat_kernel(const float* __restrict__ query, const float* __restrict__ h,
                              __half* __restrict__ out,
                              const float* __restrict__ g, const float* __restrict__ b) {
    int row = blockIdx.x * 8 + (threadIdx.x >> 5);
    int bb = row / NTOK_, sidx = row % NTOK_;
    const float* x = (sidx == 0) ? (query + (long)bb * D_)
                                 : (h + ((long)(bb * N_) + sidx - 1) * D_);
    ln_row_warp(x, out + (long)row * D_, g, b);
}

// small-row LN (query: 32 rows)
__global__ void ln_small_kernel(const float* __restrict__ in, __half* __restrict__ out,
                                const float* __restrict__ g, const float* __restrict__ b) {
    long row = blockIdx.x * 8 + (threadIdx.x >> 5);
    if (row < B_) ln_row_warp(in + row * D_, out + row * D_, g, b);
}

// ---------------- cp.async helpers ----------------
__device__ __forceinline__ void cp16(void* smem_ptr, const void* gptr, bool pred) {
    uint32_t sa = (uint32_t)__cvta_generic_to_shared(smem_ptr);
    int sz = pred ? 16 : 0;
    asm volatile("cp.async.cg.shared.global [%0], [%1], 16, %2;\n" :: "r"(sa), "l"(gptr), "r"(sz));
}
__device__ __forceinline__ void cp16u(void* smem_ptr, const void* gptr) {
    uint32_t sa = (uint32_t)__cvta_generic_to_shared(smem_ptr);
    asm volatile("cp.async.cg.shared.global [%0], [%1], 16;\n" :: "r"(sa), "l"(gptr));
}
__device__ __forceinline__ void cp_commit() {
    asm volatile("cp.async.commit_group;\n" ::: "memory");
}
template<int NN>
__device__ __forceinline__ void cp_wait() {
    asm volatile("cp.async.wait_group %0;\n" :: "n"(NN) : "memory");
}

// ---------------- mbarrier helpers ----------------
__device__ __forceinline__ void mbar_init(uint32_t a, uint32_t cnt) {
    asm volatile("mbarrier.init.shared.b64 [%0], %1;" :: "r"(a), "r"(cnt) : "memory");
}
__device__ __forceinline__ void mbar_arrive(uint32_t a) {
    asm volatile("mbarrier.arrive.shared.b64 _, [%0];" :: "r"(a) : "memory");
}
__device__ __forceinline__ void cpasync_mbar_arrive(uint32_t a) {
    asm volatile("cp.async.mbarrier.arrive.noinc.shared.b64 [%0];" :: "r"(a) : "memory");
}
__device__ __forceinline__ void mbar_wait(uint32_t a, uint32_t parity) {
    uint32_t done = 0;
    while (!done) {
        asm volatile("{\n\t.reg .pred p;\n\t"
            "mbarrier.try_wait.parity.acquire.cta.shared::cta.b64 p, [%1], %2, 0x989680;\n\t"
            "selp.b32 %0, 1, 0, p;\n\t}" : "=r"(done) : "r"(a), "r"(parity) : "memory");
    }
}

// ---------------- ldmatrix helpers ----------------
__device__ __forceinline__ void ldsm_x4(unsigned r[4], uint32_t addr) {
    asm volatile("ldmatrix.sync.aligned.m8n8.x4.shared.b16 {%0,%1,%2,%3}, [%4];"
        : "=r"(r[0]), "=r"(r[1]), "=r"(r[2]), "=r"(r[3]) : "r"(addr));
}
__device__ __forceinline__ void ldsm_x4t(unsigned r[4], uint32_t addr) {
    asm volatile("ldmatrix.sync.aligned.m8n8.x4.trans.shared.b16 {%0,%1,%2,%3}, [%4];"
        : "=r"(r[0]), "=r"(r[1]), "=r"(r[2]), "=r"(r[3]) : "r"(addr));
}

// ---------------- fp16 tensor-core mma ----------------
__device__ __forceinline__ void mma_f16(float c[4], const unsigned a[4], const unsigned b[2]) {
    asm volatile(
        "mma.sync.aligned.m16n8k16.row.col.f32.f16.f16.f32 "
        "{%0,%1,%2,%3}, {%4,%5,%6,%7}, {%8,%9}, {%0,%1,%2,%3};\n"
        : "+f"(c[0]), "+f"(c[1]), "+f"(c[2]), "+f"(c[3])
        : "r"(a[0]), "r"(a[1]), "r"(a[2]), "r"(a[3]), "r"(b[0]), "r"(b[1]));
}

__device__ __forceinline__ unsigned pk2(float a, float b) {
    __half2 x = __floats2half2_rn(a, b);
    return *(unsigned*)&x;
}

// ---------------- fused attention ----------------
#define FA_SMEM ((128*72 + 2*256*72) * 2 + 256*4 + 128*4)

__global__ void __launch_bounds__(256, 1) fused_attn(
    const __half* __restrict__ qkv, const float* __restrict__ interT,
    const void* __restrict__ mask, __half* __restrict__ ao)
{
    extern __shared__ __half sm[];
    __half* Qs = sm;
    __half* Ks = sm + 128*72;
    __half* Vs = sm + 128*72 + 256*72;
    float* kadd = (float*)(sm + 128*72 + 2*256*72);
    float* qmsk = kadd + 256;

    const int q0 = blockIdx.x * 128;
    const int bh = blockIdx.y;
    const int b = bh >> 3, h = bh & 7;
    const int tid = threadIdx.x, wid = tid >> 5, lane = tid & 31;
    const int g = lane >> 2, tg = lane & 3;

    const __half* qbase = qkv + (long)b * N_ * QKVW_ + h * DH_;

    #pragma unroll
    for (int i = 0; i < 4; i++) {
        int c = tid + i * 256;
        int row = c >> 3, ch = (c & 7) * 8;
        cp16u(Qs + row * 72 + ch, qbase + (long)(q0 + row) * QKVW_ + ch);
    }
    #pragma unroll
    for (int i = 0; i < 8; i++) {
        int c = tid + i * 256;
        int row = c >> 3, ch = (c & 7) * 8;
        cp16u(Ks + row * 72 + ch, qbase + 512  + (long)row * QKVW_ + ch);
        cp16u(Vs + row * 72 + ch, qbase + 1024 + (long)row * QKVW_ + ch);
    }
    kadd[tid] = mget(mask, b * N_ + tid) ? 0.f : -1e9f;
    if (tid < 128) qmsk[tid] = mget(mask, b * N_ + q0 + tid) ? 1.f : 0.f;
    cp_commit();
    cp_wait<0>();
    __syncthreads();

    const uint32_t Qu = (uint32_t)__cvta_generic_to_shared(Qs);
    const uint32_t Ku = (uint32_t)__cvta_generic_to_shared(Ks);
    const uint32_t Vu = (uint32_t)__cvta_generic_to_shared(Vs);
    const int lrow  = (lane & 7) + ((lane >> 3) & 1) * 8;
    const int lkof  = (lane >> 4) * 8;
    const int tkrow = (lane & 7) + (lane >> 4) * 8;
    const int tncol = ((lane >> 3) & 1) * 8;

    float sacc[32][4];
    #pragma unroll
    for (int nt = 0; nt < 32; nt++)
        #pragma unroll
        for (int r = 0; r < 4; r++) sacc[nt][r] = 0.f;

    #pragma unroll
    for (int kt = 0; kt < 4; kt++) {
        unsigned af[4];
        ldsm_x4(af, Qu + (uint32_t)(((wid * 16 + lrow) * 72 + kt * 16 + lkof) * 2));
        #pragma unroll
        for (int ntp = 0; ntp < 16; ntp++) {
            unsigned r[4];
            ldsm_x4(r, Ku + (uint32_t)(((ntp * 16 + lrow) * 72 + kt * 16 + lkof) * 2));
            unsigned b0[2] = {r[0], r[2]}, b1[2] = {r[1], r[3]};
            mma_f16(sacc[2 * ntp],     af, b0);
            mma_f16(sacc[2 * ntp + 1], af, b1);
        }
    }

    const int qrow = q0 + wid * 16 + g;
    const float* ig  = interT + ((long)bh * N_ + qrow) * N_;
    const float* ig8 = ig + 8L * N_;
    const bool qm0 = qmsk[wid * 16 + g]     != 0.f;
    const bool qm1 = qmsk[wid * 16 + g + 8] != 0.f;

    float mx0 = -3.0e38f, mx1 = -3.0e38f;
    #pragma unroll
    for (int nt = 0; nt < 32; nt++) {
        int col = nt * 8 + 2 * tg;
        float a0 = kadd[col], a1 = kadd[col + 1];
        float2 i0 = *(const float2*)(ig  + col);
        float2 i1 = *(const float2*)(ig8 + col);
        float v0 = fmaf(sacc[nt][0], 0.125f, i0.x) + (qm0 ? a0 : -1e9f);
        float v1 = fmaf(sacc[nt][1], 0.125f, i0.y) + (qm0 ? a1 : -1e9f);
        float v2 = fmaf(sacc[nt][2], 0.125f, i1.x) + (qm1 ? a0 : -1e9f);
        float v3 = fmaf(sacc[nt][3], 0.125f, i1.y) + (qm1 ? a1 : -1e9f);
        sacc[nt][0] = v0; sacc[nt][1] = v1; sacc[nt][2] = v2; sacc[nt][3] = v3;
        mx0 = fmaxf(mx0, fmaxf(v0, v1));
        mx1 = fmaxf(mx1, fmaxf(v2, v3));
    }
    #pragma unroll
    for (int o = 1; o <= 2; o <<= 1) {
        mx0 = fmaxf(mx0, __shfl_xor_sync(0xffffffffu, mx0, o));
        mx1 = fmaxf(mx1, __shfl_xor_sync(0xffffffffu, mx1, o));
    }
    float s0 = 0.f, s1 = 0.f;
    #pragma unroll
    for (int nt = 0; nt < 32; nt++) {
        float e0 = __expf(sacc[nt][0] - mx0), e1 = __expf(sacc[nt][1] - mx0);
        float e2 = __expf(sacc[nt][2] - mx1), e3 = __expf(sacc[nt][3] - mx1);
        sacc[nt][0] = e0; sacc[nt][1] = e1; sacc[nt][2] = e2; sacc[nt][3] = e3;
        s0 += e0 + e1; s1 += e2 + e3;
    }
    #pragma unroll
    for (int o = 1; o <= 2; o <<= 1) {
        s0 += __shfl_xor_sync(0xffffffffu, s0, o);
        s1 += __shfl_xor_sync(0xffffffffu, s1, o);
    }

    float oacc[8][4];
    #pragma unroll
    for (int nt = 0; nt < 8; nt++)
        #pragma unroll
        for (int r = 0; r < 4; r++) oacc[nt][r] = 0.f;

    #pragma unroll
    for (int kt = 0; kt < 16; kt++) {
        unsigned ph[4];
        ph[0] = pk2(sacc[2 * kt][0],     sacc[2 * kt][1]);
        ph[1] = pk2(sacc[2 * kt][2],     sacc[2 * kt][3]);
        ph[2] = pk2(sacc[2 * kt + 1][0], sacc[2 * kt + 1][1]);
        ph[3] = pk2(sacc[2 * kt + 1][2], sacc[2 * kt + 1][3]);
        #pragma unroll
        for (int ntp = 0; ntp < 4; ntp++) {
            unsigned r[4];
            ldsm_x4t(r, Vu + (uint32_t)(((kt * 16 + tkrow) * 72 + ntp * 16 + tncol) * 2));
            unsigned b0[2] = {r[0], r[2]}, b1[2] = {r[1], r[3]};
            mma_f16(oacc[2 * ntp],     ph, b0);
            mma_f16(oacc[2 * ntp + 1], ph, b1);
        }
    }

    float inv0 = 1.f / s0, inv1 = 1.f / s1;
    __half* aob = ao + ((long)b * N_ + qrow) * D_ + h * DH_;
    #pragma unroll
    for (int nt = 0; nt < 8; nt++) {
        int col = nt * 8 + 2 * tg;
        __half2 v0 = __floats2half2_rn(oacc[nt][0] * inv0, oacc[nt][1] * inv0);
        __half2 v1 = __floats2half2_rn(oacc[nt][2] * inv1, oacc[nt][3] * inv1);
        *(__half2*)(aob + col) = v0;
        *(__half2*)(aob + 8L * D_ + col) = v1;
    }
}

// ---------------- fp16 GEMM: BM=256 BN=128 BK=64, 512 thr, 4-stage mbarrier ring ----------------
#define GSTG 4
#define A_ST 18432
#define B_ST 9216
#define AB_OFF (GSTG * A_ST)
#define HSMEM_BYTES ((GSTG * (A_ST + B_ST)) * 2)   // 221184 B

template<int TRANSB, int CHK>
__global__ void __launch_bounds__(512, 1) gemm_h(
    const __half* __restrict__ A, const __half* __restrict__ Bm, void* __restrict__ Cv,
    int M, int Nn, int K, int lda, int ldb, int ldc,
    int zdiv, long sA1, long sA2, long sB1, long sB2, long sC1, long sC2,
    const float* __restrict__ bias, const float* __restrict__ res, int ldr,
    long sR1, long sR2, int act, int cmode)
{
    extern __shared__ __half dynh[];
    __shared__ __align__(8) unsigned long long mbars[2 * GSTG];
    const uint32_t dyn_u = (uint32_t)__cvta_generic_to_shared(dynh);
    const uint32_t mb_u  = (uint32_t)__cvta_generic_to_shared(mbars);

    int z = blockIdx.z;
    long z1 = z / zdiv, z2 = z % zdiv;
    A  += z1 * sA1 + z2 * sA2;
    Bm += z1 * sB1 + z2 * sB2;
    long coff = z1 * sC1 + z2 * sC2;
    if (res) res += z1 * sR1 + z2 * sR2;

    const int tid  = threadIdx.x;
    const int wid  = tid >> 5, lane = tid & 31;
    const int wM   = wid >> 2, wN = wid & 3;
    const int g    = lane >> 2, tg = lane & 3;
    const int m0   = blockIdx.y * 256, n0 = blockIdx.x * 128;

    if (tid == 0) {
        #pragma unroll
        for (int s = 0; s < GSTG; s++) {
            mbar_init(mb_u + s * 8, 512);
            mbar_init(mb_u + 32 + s * 8, 512);
        }
    }
    __syncthreads();

    float acc[4][4][4];
    #pragma unroll
    for (int i = 0; i < 4; i++)
        #pragma unroll
        for (int j = 0; j < 4; j++)
            #pragma unroll
            for (int r = 0; r < 4; r++) acc[i][j][r] = 0.f;

    auto load_stage = [&](int buf, int k0) {
        #pragma unroll
        for (int i = 0; i < 4; i++) {
            int c = tid + i * 512;
            int row = c >> 3, col = (c & 7) << 3;
            if (CHK) {
                bool p = (m0 + row) < M;
                const __half* gp = p ? (A + (long)(m0 + row) * lda + k0 + col) : A;
                cp16(dynh + buf * A_ST + row * 72 + col, gp, p);
            } else {
                cp16u(dynh + buf * A_ST + row * 72 + col,
                      A + (long)(m0 + row) * lda + k0 + col);
            }
        }
        if (TRANSB) {
            #pragma unroll
            for (int i = 0; i < 2; i++) {
                int c = tid + i * 512;
                int row = c >> 3, col = (c & 7) << 3;
                if (CHK) {
                    bool p = (n0 + row) < Nn;
                    const __half* gp = p ? (Bm + (long)(n0 + row) * ldb + k0 + col) : Bm;
                    cp16(dynh + AB_OFF + buf * B_ST + row * 72 + col, gp, p);
                } else {
                    cp16u(dynh + AB_OFF + buf * B_ST + row * 72 + col,
                          Bm + (long)(n0 + row) * ldb + k0 + col);
                }
            }
        } else {
            #pragma unroll
            for (int i = 0; i < 2; i++) {
                int c = tid + i * 512;
                int row = c >> 4, col = (c & 15) << 3;
                if (CHK) {
                    bool p = (n0 + col) < Nn;
                    const __half* gp = p ? (Bm + (long)(k0 + row) * ldb + n0 + col) : Bm;
                    cp16(dynh + AB_OFF + buf * B_ST + row * 136 + col, gp, p);
                } else {
                    cp16u(dynh + AB_OFF + buf * B_ST + row * 136 + col,
                          Bm + (long)(k0 + row) * ldb + n0 + col);
                }
            }
        }
    };

    const int lrow = (lane & 7) + ((lane >> 3) & 1) * 8;
    const int lkof = (lane >> 4) * 8;
    const int tkrow = (lane & 7) + (lane >> 4) * 8;
    const int tncol = ((lane >> 3) & 1) * 8;

    auto compute = [&](int buf) {
        const uint32_t As = dyn_u + (uint32_t)(buf * A_ST * 2);
        const uint32_t Bs = dyn_u + (uint32_t)((AB_OFF + buf * B_ST) * 2);
        #pragma unroll
        for (int ks = 0; ks < 64; ks += 16) {
            unsigned af[4][4], bf[4][2];
            #pragma unroll
            for (int mt = 0; mt < 4; mt++)
                ldsm_x4(af[mt],
                        As + (uint32_t)(((wM * 64 + mt * 16 + lrow) * 72 + ks + lkof) * 2));
            #pragma unroll
            for (int ntp = 0; ntp < 2; ntp++) {
                unsigned r[4];
                if (TRANSB) {
                    ldsm_x4(r, Bs + (uint32_t)(((wN * 32 + ntp * 16 + lrow) * 72
                                               + ks + lkof) * 2));
                } else {
                    ldsm_x4t(r, Bs + (uint32_t)(((ks + tkrow) * 136
                                                + wN * 32 + ntp * 16 + tncol) * 2));
                }
                bf[2 * ntp][0] = r[0]; bf[2 * ntp + 1][0] = r[1];
                bf[2 * ntp][1] = r[2]; bf[2 * ntp + 1][1] = r[3];
            }
            #pragma unroll
            for (int mt = 0; mt < 4; mt++)
                #pragma unroll
                for (int nt = 0; nt < 4; nt++)
                    mma_f16(acc[mt][nt], af[mt], bf[nt]);
        }
    };

    const int KT = K >> 6;
    #pragma unroll
    for (int s = 0; s < GSTG - 1; s++) {
        load_stage(s, s * 64);
        cpasync_mbar_arrive(mb_u + s * 8);
    }
    for (int kt = 0; kt < KT; kt++) {
        int b = kt & (GSTG - 1);
        mbar_wait(mb_u + b * 8, (kt >> 2) & 1);
        compute(b);
        mbar_arrive(mb_u + 32 + b * 8);
        int pf = kt + GSTG - 1;
        if (pf < KT) {
            int pb = pf & (GSTG - 1);
            if (pf >= GSTG)
                mbar_wait(mb_u + 32 + pb * 8, ((pf >> 2) - 1) & 1);
            load_stage(pb, pf * 64);
            cpasync_mbar_arrive(mb_u + pb * 8);
        }
    }

    #pragma unroll
    for (int mt = 0; mt < 4; mt++) {
        #pragma unroll
        for (int nt = 0; nt < 4; nt++) {
            int m = m0 + wM * 64 + mt * 16 + g;
            int n = n0 + wN * 32 + nt * 8 + tg * 2;
            if (CHK && n >= Nn) continue;
            float bx = 0.f, by = 0.f;
            if (bias) { bx = bias[n]; by = bias[n + 1]; }
            #pragma unroll
            for (int half = 0; half < 2; half++) {
                int mm = m + half * 8;
                if (CHK && mm >= M) continue;
                float2 v = make_float2(acc[mt][nt][half * 2], acc[mt][nt][half * 2 + 1]);
                if (bias) { v.x += bx; v.y += by; }
                if (act) {
                    v.x = 0.5f * v.x * (1.f + erff(v.x * 0.70710678118654752f));
                    v.y = 0.5f * v.y * (1.f + erff(v.y * 0.70710678118654752f));
                }
                if (res) {
                    float2 r = *(const float2*)(res + (long)mm * ldr + n);
                    v.x += r.x; v.y += r.y;
                }
                if (cmode) {
                    __half2 hv = __floats2half2_rn(v.x, v.y);
                    *(__half2*)((__half*)Cv + coff + (long)mm * ldc + n) = hv;
                } else {
                    *(float2*)((float*)Cv + coff + (long)mm * ldc + n) = v;
                }
            }
        }
    }
}

// ---------------- class attention core ----------------
__global__ void cattn_kernel(const float* __restrict__ qh, const float* __restrict__ khvh,
                             __half* __restrict__ co, const void* __restrict__ mask) {
    int z = blockIdx.x;
    int b = z / H_, h = z % H_;
    int tid = threadIdx.x;
    __shared__ float a[NTOK_];
    __shared__ float red[4];
    const float* qv = qh + (long)b * D_ + h * DH_;
    float lmax = -3.0e38f;
    for (int sidx = tid; sidx < NTOK_; sidx += 128) {
        const float* kv = khvh + ((long)(b * NTOK_ + sidx)) * KVW_ + h * DH_;
        float sc = 0.f;
        #pragma unroll
        for (int d = 0; d < DH_; d++) sc += qv[d] * kv[d];
        sc = sc * 0.125f + ((sidx == 0 || mget(mask, b * N_ + sidx - 1)) ? 0.f : -1e9f);
        a[sidx] = sc;
        lmax = fmaxf(lmax, sc);
    }
    #pragma unroll
    for (int off = 16; off; off >>= 1) lmax = fmaxf(lmax, __shfl_xor_sync(0xffffffffu, lmax, off));
    if ((tid & 31) == 0) red[tid >> 5] = lmax;
    __syncthreads();
    float m = fmaxf(fmaxf(red[0], red[1]), fmaxf(red[2], red[3]));
    __syncthreads();
    float lsum = 0.f;
    for (int sidx = tid; sidx < NTOK_; sidx += 128) {
        float e = __expf(a[sidx] - m);
        a[sidx] = e;
        lsum += e;
    }
    #pragma unroll
    for (int off = 16; off; off >>= 1) lsum += __shfl_xor_sync(0xffffffffu, lsum, off);
    if ((tid & 31) == 0) red[tid >> 5] = lsum;
    __syncthreads();
    float inv = 1.f / (red[0] + red[1] + red[2] + red[3]);
    if (tid < DH_) {
        float o = 0.f;
        for (int sidx = 0; sidx < NTOK_; sidx++)
            o += a[sidx] * khvh[((long)(b * NTOK_ + sidx)) * KVW_ + 512 + h * DH_ + tid];
        co[(long)b * D_ + h * DH_ + tid] = __float2half(o * inv);
    }
}

// ---------------- host-side launch helpers ----------------
static void launch_gemm(const __half* A, const __half* Bm, void* C,
                        int M, int Nn, int K, int lda, int ldb, int ldc,
                        const float* bias, const float* res, int ldr, int act, int cmode,
                        int nz, int zdiv,
                        long sA1, long sA2, long sB1, long sB2, long sC1, long sC2,
                        long sR1, long sR2, bool transb) {
    dim3 grid((Nn + 127) / 128, (M + 255) / 256, nz);
    bool exact = (M % 256 == 0) && (Nn % 128 == 0);
    if (transb) {
        if (exact)
            gemm_h<1,0><<<grid, 512, HSMEM_BYTES>>>(A, Bm, C, M, Nn, K, lda, ldb, ldc,
                zdiv, sA1, sA2, sB1, sB2, sC1, sC2, bias, res, ldr, sR1, sR2, act, cmode);
        else
            gemm_h<1,1><<<grid, 512, HSMEM_BYTES>>>(A, Bm, C, M, Nn, K, lda, ldb, ldc,
                zdiv, sA1, sA2, sB1, sB2, sC1, sC2, bias, res, ldr, sR1, sR2, act, cmode);
    } else {
        if (exact)
            gemm_h<0,0><<<grid, 512, HSMEM_BYTES>>>(A, Bm, C, M, Nn, K, lda, ldb, ldc,
                zdiv, sA1, sA2, sB1, sB2, sC1, sC2, bias, res, ldr, sR1, sR2, act, cmode);
        else
            gemm_h<0,1><<<grid, 512, HSMEM_BYTES>>>(A, Bm, C, M, Nn, K, lda, ldb, ldc,
                zdiv, sA1, sA2, sB1, sB2, sC1, sC2, bias, res, ldr, sR1, sR2, act, cmode);
    }
}

static void launch_gemm_simple(const __half* A, const __half* Bm, void* C,
                               int M, int Nn, int K, int lda, int ldb, int ldc,
                               const float* bias, const float* res, int ldr,
                               int act, int cmode) {
    launch_gemm(A, Bm, C, M, Nn, K, lda, ldb, ldc, bias, res, ldr, act, cmode,
                1, 1, 0, 0, 0, 0, 0, 0, 0, 0, true);
}

extern "C" void kernel_launch(void* const* d_in, const int* in_sizes, int n_in,
                              void* d_out, int out_size) {
    const float* x       = (const float*)d_in[0];
    const float* inter   = (const float*)d_in[1];
    const float* ctok    = (const float*)d_in[2];
    const float* p_ln1_g = (const float*)d_in[3];
    const float* p_ln1_b = (const float*)d_in[4];
    const float* p_wq    = (const float*)d_in[5];
    const float* p_wk    = (const float*)d_in[6];
    const float* p_wv    = (const float*)d_in[7];
    const float* p_wo    = (const float*)d_in[8];
    const float* p_ln2_g = (const float*)d_in[9];
    const float* p_ln2_b = (const float*)d_in[10];
    const float* p_w1    = (const float*)d_in[11];
    const float* p_b1    = (const float*)d_in[12];
    const float* p_w2    = (const float*)d_in[13];
    const float* p_b2    = (const float*)d_in[14];
    const float* c_ln1_g = (const float*)d_in[15];
    const float* c_ln1_b = (const float*)d_in[16];
    const float* c_qk    = (const float*)d_in[17];
    const float* c_qb    = (const float*)d_in[18];
    const float* c_kk    = (const float*)d_in[19];
    const float* c_kb    = (const float*)d_in[20];
    const float* c_vk    = (const float*)d_in[21];
    const float* c_vb    = (const float*)d_in[22];
    const float* c_ok    = (const float*)d_in[23];
    const float* c_ob    = (const float*)d_in[24];
    const float* c_ln2_g = (const float*)d_in[25];
    const float* c_ln2_b = (const float*)d_in[26];
    const float* c_w1    = (const float*)d_in[27];
    const float* c_b1    = (const float*)d_in[28];
    const float* c_w2    = (const float*)d_in[29];
    const float* c_b2    = (const float*)d_in[30];
    const void*  mask    = d_in[31];

    cudaFuncSetAttribute(gemm_h<0,0>, cudaFuncAttributeMaxDynamicSharedMemorySize, HSMEM_BYTES);
    cudaFuncSetAttribute(gemm_h<0,1>, cudaFuncAttributeMaxDynamicSharedMemorySize, HSMEM_BYTES);
    cudaFuncSetAttribute(gemm_h<1,0>, cudaFuncAttributeMaxDynamicSharedMemorySize, HSMEM_BYTES);
    cudaFuncSetAttribute(gemm_h<1,1>, cudaFuncAttributeMaxDynamicSharedMemorySize, HSMEM_BYTES);
    cudaFuncSetAttribute(fused_attn, cudaFuncAttributeMaxDynamicSharedMemorySize, FA_SMEM);

    float *h, *interT, *khvh, *qh, *query, *ckvb;
    __half *hn, *qkv, *ao, *t, *cn, *co, *queryh, *cfn, *cff;
    __half *wqkvT, *woT, *w1T, *w2T, *cqkT, *ckvT, *cokT, *cw1T, *cw2T;
    cudaGetSymbolAddress((void**)&h,     g_h);
    cudaGetSymbolAddress((void**)&hn,    g_hn);
    cudaGetSymbolAddress((void**)&qkv,   g_qkv);
    cudaGetSymbolAddress((void**)&ao,    g_ao);
    cudaGetSymbolAddress((void**)&interT,g_interT);
    cudaGetSymbolAddress((void**)&t,     g_t);
    cudaGetSymbolAddress((void**)&cn,    g_cn);
    cudaGetSymbolAddress((void**)&khvh,  g_khvh);
    cudaGetSymbolAddress((void**)&qh,    g_qh);
    cudaGetSymbolAddress((void**)&co,    g_co);
    cudaGetSymbolAddress((void**)&query, g_query);
    cudaGetSymbolAddress((void**)&queryh,g_queryh);
    cudaGetSymbolAddress((void**)&cfn,   g_cfn);
    cudaGetSymbolAddress((void**)&cff,   g_cff);
    cudaGetSymbolAddress((void**)&ckvb,  g_ckvb);
    cudaGetSymbolAddress((void**)&wqkvT, g_wqkvT);
    cudaGetSymbolAddress((void**)&woT,   g_woT);
    cudaGetSymbolAddress((void**)&w1T,   g_w1T);
    cudaGetSymbolAddress((void**)&w2T,   g_w2T);
    cudaGetSymbolAddress((void**)&cqkT,  g_cqkT);
    cudaGetSymbolAddress((void**)&ckvT,  g_ckvT);
    cudaGetSymbolAddress((void**)&cokT,  g_cokT);
    cudaGetSymbolAddress((void**)&cw1T,  g_cw1T);
    cudaGetSymbolAddress((void**)&cw2T,  g_cw2T);

    // prep
    {
        WTable w;
        auto set = [&](int i, const float* s, __half* d, int K, int N, int layers, long dStride) {
            w.src[i] = s; w.dst[i] = d; w.K[i] = K; w.N[i] = N;
            w.sS[i] = (long)K * N;
            w.dS[i] = dStride;
            int tiles = (K / 64) * (N / 64) * layers;
            w.base[i + 1] = w.base[i] + tiles;
        };
        w.base[0] = 0;
        set(0,  p_wq, wqkvT + 0L * D_,    D_, D_, L_,  (long)QKVW_ * D_);
        set(1,  p_wk, wqkvT + 512L * D_,  D_, D_, L_,  (long)QKVW_ * D_);
        set(2,  p_wv, wqkvT + 1024L * D_, D_, D_, L_,  (long)QKVW_ * D_);
        set(3,  p_wo, woT,  D_, D_, L_,  (long)D_ * D_);
        set(4,  p_w1, w1T,  D_, F_, L_,  (long)D_ * F_);
        set(5,  p_w2, w2T,  F_, D_, L_,  (long)F_ * D_);
        set(6,  c_qk, cqkT, D_, D_, LC_, (long)D_ * D_);
        set(7,  c_kk, ckvT + 0L * D_,   D_, D_, LC_, (long)KVW_ * D_);
        set(8,  c_vk, ckvT + 512L * D_, D_, D_, LC_, (long)KVW_ * D_);
        set(9,  c_ok, cokT, D_, D_, LC_, (long)D_ * D_);
        set(10, c_w1, cw1T, D_, F_, LC_, (long)D_ * F_);
        transpose_all<<<w.base[NWT], dim3(32, 8)>>>(w);
    }
    {
        WTable w2t;
        w2t.base[0] = 0;
        for (int i = 0; i < NWT; i++) { w2t.src[i] = c_w2; w2t.dst[i] = cw2T;
            w2t.K[i] = F_; w2t.N[i] = D_; w2t.sS[i] = (long)F_ * D_; w2t.dS[i] = (long)D_ * F_;
            w2t.base[i + 1] = (i == 0) ? (F_/64)*(D_/64)*LC_ : w2t.base[i]; }
        transpose_all<<<(F_/64)*(D_/64)*LC_, dim3(32, 8)>>>(w2t);
    }
    ckvb_kernel<<<(LC_*KVW_ + 255) / 256, 256>>>(c_kb, c_vb);

    // -------- particle transformer layers --------
    for (int l = 0; l < L_; l++) {
        const float* hin = (l == 0) ? x : h;
        ln_kernel<<<B_*N_/8, 256>>>(hin, hn, p_ln1_g + (long)l * D_, p_ln1_b + (long)l * D_);

        // fused QKV -> qkv[M, 1536] (half)
        launch_gemm_simple(hn, wqkvT + (long)l * QKVW_ * D_, qkv,
                           B_*N_, QKVW_, D_, D_, D_, QKVW_, nullptr, nullptr, 0, 0, 1);

        if (l == 0) {
            transpose_inter<<<B_*N_, 256>>>(inter, interT);
            detect_mask_kernel<<<1, 1>>>((const unsigned int*)mask);
        }

        // fused score+softmax+AV -> ao (half)
        fused_attn<<<dim3(2, B_*H_), 256, FA_SMEM>>>(qkv, interT, mask, ao);

        // h = hin + ao @ Wo
        launch_gemm_simple(ao, woT + (long)l * D_ * D_, h,
                           B_*N_, D_, D_, D_, D_, D_, nullptr, hin, D_, 0, 0);

        // FFN
        ln_kernel<<<B_*N_/8, 256>>>(h, hn, p_ln2_g + (long)l * D_, p_ln2_b + (long)l * D_);
        launch_gemm_simple(hn, w1T + (long)l * F_ * D_, t,
                           B_*N_, F_, D_, D_, D_, F_, p_b1 + (long)l * F_, nullptr, 0, 1, 1);
        launch_gemm_simple(t, w2T + (long)l * D_ * F_, h,
                           B_*N_, D_, F_, F_, F_, D_, p_b2 + (long)l * D_, h, D_, 0, 0);
    }

    // -------- class attention layers --------
    bcast_token_kernel<<<(B_*D_ + 255) / 256, 256>>>(ctok);
    for (int l = 0; l < LC_; l++) {
        ln_cat_kernel<<<B_*NTOK_/8, 256>>>(query, h, cn,
                                           c_ln1_g + (long)l * D_, c_ln1_b + (long)l * D_);
        f2h_kernel<<<(B_*D_ + 255) / 256, 256>>>(query, queryh, B_*D_);
        launch_gemm_simple(queryh, cqkT + (long)l * D_ * D_, qh, B_, D_, D_, D_, D_, D_,
                           c_qb + (long)l * D_, nullptr, 0, 0, 0);
        launch_gemm_simple(cn, ckvT + (long)l * KVW_ * D_, khvh, B_*NTOK_, KVW_, D_,
                           D_, D_, KVW_, ckvb + (long)l * KVW_, nullptr, 0, 0, 0);

        cattn_kernel<<<B_*H_, 128>>>(qh, khvh, co, mask);

        launch_gemm_simple(co, cokT + (long)l * D_ * D_, query, B_, D_, D_, D_, D_, D_,
                           c_ob + (long)l * D_, query, D_, 0, 0);

        ln_small_kernel<<<(B_ + 7) / 8, 256>>>(query, cfn,
                                               c_ln2_g + (long)l * D_, c_ln2_b + (long)l * D_);
        launch_gemm_simple(cfn, cw1T + (long)l * F_ * D_, cff, B_, F_, D_, D_, D_, F_,
                           c_b1 + (long)l * F_, nullptr, 0, 1, 1);
        launch_gemm_simple(cff, cw2T + (long)l * D_ * F_, query, B_, D_, F_, F_, F_, D_,
                           c_b2 + (long)l * D_, query, D_, 0, 0);
    }

    copy_kernel<<<(B_*D_ + 255) / 256, 256>>>(query, (float*)d_out, B_*D_);
}

// round 15
// speedup vs baseline: 1.0202x; 1.0202x over previous
#include <cuda_runtime.h>
#include <cuda_fp16.h>
#include <math.h>
#include <stdint.h>

#define B_ 32
#define N_ 256
#define D_ 512
#define H_ 8
#define DH_ 64
#define F_ 2048
#define L_ 8
#define LC_ 2
#define NTOK_ 257
#define QKVW_ 1536
#define KVW_ 1024

// ---------------- scratch (device globals; no allocation allowed) ----------------
static __device__ float  g_h  [B_*N_*D_];
static __device__ __half g_hn [B_*N_*D_];
static __device__ __half g_qkv[B_*N_*QKVW_];
static __device__ __half g_ao [B_*N_*D_];
static __device__ __half g_interT[B_*H_*N_*N_];
static __device__ __half g_t  [B_*N_*F_];
static __device__ __half g_cn [B_*NTOK_*D_];
static __device__ float  g_khvh[B_*NTOK_*KVW_];
static __device__ float  g_qh [B_*D_];
static __device__ __half g_co [B_*D_];
static __device__ float  g_query[B_*D_];
static __device__ __half g_queryh[B_*D_];
static __device__ __half g_cfn[B_*D_];
static __device__ __half g_cff[B_*F_];
static __device__ float  g_ckvb[LC_*KVW_];
static __device__ int    g_mask_mode;

// transposed fp16 weights: [N][K] row-major
static __device__ __half g_wqkvT[L_*QKVW_*D_];
static __device__ __half g_woT [L_*D_*D_];
static __device__ __half g_w1T [L_*F_*D_];
static __device__ __half g_w2T [L_*D_*F_];
static __device__ __half g_cqkT[LC_*D_*D_];
static __device__ __half g_ckvT[LC_*KVW_*D_];
static __device__ __half g_cokT[LC_*D_*D_];
static __device__ __half g_cw1T[LC_*F_*D_];
static __device__ __half g_cw2T[LC_*D_*F_];

// ---------------- mask dtype detection ----------------
__global__ void detect_mask_kernel(const unsigned int* m) {
    unsigned int w = m[0];
    int mode = 0;
    if (w == 0x01010101u) mode = 1;
    else if (w == 0x3F800000u) mode = 2;
    g_mask_mode = mode;
}

__device__ __forceinline__ bool mget(const void* m, int idx) {
    int mode = g_mask_mode;
    if (mode == 1) return ((const unsigned char*)m)[idx] != 0;
    if (mode == 2) return ((const float*)m)[idx] != 0.0f;
    return ((const int*)m)[idx] != 0;
}

// ---------------- tiny utility kernels ----------------
__global__ void copy_kernel(const float* __restrict__ src, float* __restrict__ dst, int n) {
    int i = blockIdx.x * 256 + threadIdx.x;
    if (i < n) dst[i] = src[i];
}

__global__ void f2h_kernel(const float* __restrict__ src, __half* __restrict__ dst, int n) {
    int i = blockIdx.x * 256 + threadIdx.x;
    if (i < n) dst[i] = __float2half(src[i]);
}

__global__ void bcast_token_kernel(const float* __restrict__ tok) {
    int i = blockIdx.x * 256 + threadIdx.x;
    if (i < B_*D_) g_query[i] = tok[i % D_];
}

// combined class K/V bias
__global__ void ckvb_kernel(const float* __restrict__ kb, const float* __restrict__ vb) {
    int i = blockIdx.x * 256 + threadIdx.x;
    if (i >= LC_ * KVW_) return;
    int l = i >> 10, c = i & 1023;
    g_ckvb[i] = (c < 512) ? kb[l * 512 + c] : vb[l * 512 + c - 512];
}

// inter [B,N,N,H] f32 -> interT [B,H,N,N] f16
__global__ void transpose_inter(const float* __restrict__ inter, __half* __restrict__ interT) {
    int row = blockIdx.x;
    int b = row >> 8, qi = row & 255;
    int k = threadIdx.x;
    const float4* ip = (const float4*)(inter + ((long)row * N_ + k) * H_);
    float4 i0 = ip[0], i1 = ip[1];
    float v[8] = {i0.x, i0.y, i0.z, i0.w, i1.x, i1.y, i1.z, i1.w};
    #pragma unroll
    for (int h = 0; h < H_; h++)
        interT[((long)(b * H_ + h) * N_ + qi) * N_ + k] = __float2half(v[h]);
}

// ---------------- all weight transposes in ONE launch (64x64 tiles) ----------------
#define NWT 11
struct WTable {
    const float* src[NWT];
    __half*      dst[NWT];
    int          K[NWT], N[NWT];
    long         sS[NWT], dS[NWT];
    int          base[NWT + 1];
};

__global__ void transpose_all(WTable w) {
    __shared__ float tile[64][65];
    int bx = blockIdx.x;
    int gsel = 0;
    #pragma unroll
    for (int i = 1; i < NWT; i++) if (bx >= w.base[i]) gsel = i;
    int local = bx - w.base[gsel];
    int K = w.K[gsel], N = w.N[gsel];
    int ncols = N >> 6;
    int tpl = (K >> 6) * ncols;
    int layer = local / tpl;
    int rem = local % tpl;
    int k0 = (rem / ncols) * 64, n0 = (rem % ncols) * 64;
    const float* src = w.src[gsel] + (long)layer * w.sS[gsel];
    __half* dst = w.dst[gsel] + (long)layer * w.dS[gsel];
    int t = threadIdx.y * 32 + threadIdx.x;
    #pragma unroll
    for (int i = 0; i < 4; i++) {
        int r = i * 16 + (t >> 4);
        int c = (t & 15) * 4;
        float4 v = *(const float4*)(src + (long)(k0 + r) * N + n0 + c);
        tile[r][c] = v.x; tile[r][c + 1] = v.y; tile[r][c + 2] = v.z; tile[r][c + 3] = v.w;
    }
    __syncthreads();
    #pragma unroll
    for (int i = 0; i < 8; i++) {
        int n = i * 8 + (t >> 5);
        int kc = (t & 31) * 2;
        __half2 hv = __floats2half2_rn(tile[kc][n], tile[kc + 1][n]);
        *(__half2*)(dst + (long)(n0 + n) * K + k0 + kc) = hv;
    }
}

// ---------------- LayerNorm (eps = 1e-3): one WARP per row ----------------
__device__ __forceinline__ void ln_row_warp(const float* __restrict__ x, __half* __restrict__ o,
                                            const float* __restrict__ g, const float* __restrict__ bb) {
    int lane = threadIdx.x & 31;
    float4 v[4];
    #pragma unroll
    for (int i = 0; i < 4; i++)
        v[i] = *(const float4*)(x + (i * 32 + lane) * 4);
    float s = 0.f, s2 = 0.f;
    #pragma unroll
    for (int i = 0; i < 4; i++) {
        s  += v[i].x + v[i].y + v[i].z + v[i].w;
        s2 += v[i].x*v[i].x + v[i].y*v[i].y + v[i].z*v[i].z + v[i].w*v[i].w;
    }
    #pragma unroll
    for (int off = 16; off; off >>= 1) {
        s  += __shfl_xor_sync(0xffffffffu, s,  off);
        s2 += __shfl_xor_sync(0xffffffffu, s2, off);
    }
    float mean = s * (1.f / D_);
    float var  = s2 * (1.f / D_) - mean * mean;
    float r = rsqrtf(var + 1e-3f);
    #pragma unroll
    for (int i = 0; i < 4; i++) {
        int idx = (i * 32 + lane) * 4;
        float4 g4 = *(const float4*)(g + idx);
        float4 b4 = *(const float4*)(bb + idx);
        float o0 = (v[i].x - mean) * r * g4.x + b4.x;
        float o1 = (v[i].y - mean) * r * g4.y + b4.y;
        float o2 = (v[i].z - mean) * r * g4.z + b4.z;
        float o3 = (v[i].w - mean) * r * g4.w + b4.w;
        __half2 h0 = __floats2half2_rn(o0, o1);
        __half2 h1 = __floats2half2_rn(o2, o3);
        uint2 u; u.x = *(unsigned*)&h0; u.y = *(unsigned*)&h1;
        *(uint2*)(o + idx) = u;
    }
}

__global__ void ln_kernel(const float* __restrict__ in, __half* __restrict__ out,
                          const float* __restrict__ g, const float* __restrict__ b) {
    long row = blockIdx.x * 8 + (threadIdx.x >> 5);
    ln_row_warp(in + row * D_, out + row * D_, g, b);
}

__global__ void ln_cat_kernel(const float* __restrict__ query, const float* __restrict__ h,
                              __half* __restrict__ out,
                              const float* __restrict__ g, const float* __restrict__ b) {
    int row = blockIdx.x * 8 + (threadIdx.x >> 5);
    int bb = row / NTOK_, sidx = row % NTOK_;
    const float* x = (sidx == 0) ? (query + (long)bb * D_)
                                 : (h + ((long)(bb * N_) + sidx - 1) * D_);
    ln_row_warp(x, out + (long)row * D_, g, b);
}

__global__ void ln_small_kernel(const float* __restrict__ in, __half* __restrict__ out,
                                const float* __restrict__ g, const float* __restrict__ b) {
    long row = blockIdx.x * 8 + (threadIdx.x >> 5);
    if (row < B_) ln_row_warp(in + row * D_, out + row * D_, g, b);
}

// ---------------- cp.async helpers ----------------
__device__ __forceinline__ void cp16(void* smem_ptr, const void* gptr, bool pred) {
    uint32_t sa = (uint32_t)__cvta_generic_to_shared(smem_ptr);
    int sz = pred ? 16 : 0;
    asm volatile("cp.async.cg.shared.global [%0], [%1], 16, %2;\n" :: "r"(sa), "l"(gptr), "r"(sz));
}
__device__ __forceinline__ void cp16u(void* smem_ptr, const void* gptr) {
    uint32_t sa = (uint32_t)__cvta_generic_to_shared(smem_ptr);
    asm volatile("cp.async.cg.shared.global [%0], [%1], 16;\n" :: "r"(sa), "l"(gptr));
}
__device__ __forceinline__ void cp_commit() {
    asm volatile("cp.async.commit_group;\n" ::: "memory");
}
template<int NN>
__device__ __forceinline__ void cp_wait() {
    asm volatile("cp.async.wait_group %0;\n" :: "n"(NN) : "memory");
}

// ---------------- mbarrier helpers ----------------
__device__ __forceinline__ void mbar_init(uint32_t a, uint32_t cnt) {
    asm volatile("mbarrier.init.shared.b64 [%0], %1;" :: "r"(a), "r"(cnt) : "memory");
}
__device__ __forceinline__ void mbar_arrive(uint32_t a) {
    asm volatile("mbarrier.arrive.shared.b64 _, [%0];" :: "r"(a) : "memory");
}
__device__ __forceinline__ void cpasync_mbar_arrive(uint32_t a) {
    asm volatile("cp.async.mbarrier.arrive.noinc.shared.b64 [%0];" :: "r"(a) : "memory");
}
__device__ __forceinline__ void mbar_wait(uint32_t a, uint32_t parity) {
    uint32_t done = 0;
    while (!done) {
        asm volatile("{\n\t.reg .pred p;\n\t"
            "mbarrier.try_wait.parity.acquire.cta.shared::cta.b64 p, [%1], %2, 0x989680;\n\t"
            "selp.b32 %0, 1, 0, p;\n\t}" : "=r"(done) : "r"(a), "r"(parity) : "memory");
    }
}

// ---------------- ldmatrix helpers ----------------
__device__ __forceinline__ void ldsm_x4(unsigned r[4], uint32_t addr) {
    asm volatile("ldmatrix.sync.aligned.m8n8.x4.shared.b16 {%0,%1,%2,%3}, [%4];"
        : "=r"(r[0]), "=r"(r[1]), "=r"(r[2]), "=r"(r[3]) : "r"(addr));
}
__device__ __forceinline__ void ldsm_x4t(unsigned r[4], uint32_t addr) {
    asm volatile("ldmatrix.sync.aligned.m8n8.x4.trans.shared.b16 {%0,%1,%2,%3}, [%4];"
        : "=r"(r[0]), "=r"(r[1]), "=r"(r[2]), "=r"(r[3]) : "r"(addr));
}

// ---------------- fp16 tensor-core mma ----------------
__device__ __forceinline__ void mma_f16(float c[4], const unsigned a[4], const unsigned b[2]) {
    asm volatile(
        "mma.sync.aligned.m16n8k16.row.col.f32.f16.f16.f32 "
        "{%0,%1,%2,%3}, {%4,%5,%6,%7}, {%8,%9}, {%0,%1,%2,%3};\n"
        : "+f"(c[0]), "+f"(c[1]), "+f"(c[2]), "+f"(c[3])
        : "r"(a[0]), "r"(a[1]), "r"(a[2]), "r"(a[3]), "r"(b[0]), "r"(b[1]));
}

__device__ __forceinline__ unsigned pk2(float a, float b) {
    __half2 x = __floats2half2_rn(a, b);
    return *(unsigned*)&x;
}

// ---------------- fused attention ----------------
#define FA_SMEM ((128*72 + 2*256*72) * 2 + 256*4 + 128*4)

__global__ void __launch_bounds__(256, 1) fused_attn(
    const __half* __restrict__ qkv, const __half* __restrict__ interT,
    const void* __restrict__ mask, __half* __restrict__ ao)
{
    extern __shared__ __half sm[];
    __half* Qs = sm;
    __half* Ks = sm + 128*72;
    __half* Vs = sm + 128*72 + 256*72;
    float* kadd = (float*)(sm + 128*72 + 2*256*72);
    float* qmsk = kadd + 256;

    const int q0 = blockIdx.x * 128;
    const int bh = blockIdx.y;
    const int b = bh >> 3, h = bh & 7;
    const int tid = threadIdx.x, wid = tid >> 5, lane = tid & 31;
    const int g = lane >> 2, tg = lane & 3;

    const __half* qbase = qkv + (long)b * N_ * QKVW_ + h * DH_;

    #pragma unroll
    for (int i = 0; i < 4; i++) {
        int c = tid + i * 256;
        int row = c >> 3, ch = (c & 7) * 8;
        cp16u(Qs + row * 72 + ch, qbase + (long)(q0 + row) * QKVW_ + ch);
    }
    #pragma unroll
    for (int i = 0; i < 8; i++) {
        int c = tid + i * 256;
        int row = c >> 3, ch = (c & 7) * 8;
        cp16u(Ks + row * 72 + ch, qbase + 512  + (long)row * QKVW_ + ch);
        cp16u(Vs + row * 72 + ch, qbase + 1024 + (long)row * QKVW_ + ch);
    }
    kadd[tid] = mget(mask, b * N_ + tid) ? 0.f : -1e9f;
    if (tid < 128) qmsk[tid] = mget(mask, b * N_ + q0 + tid) ? 1.f : 0.f;
    cp_commit();
    cp_wait<0>();
    __syncthreads();

    const uint32_t Qu = (uint32_t)__cvta_generic_to_shared(Qs);
    const uint32_t Ku = (uint32_t)__cvta_generic_to_shared(Ks);
    const uint32_t Vu = (uint32_t)__cvta_generic_to_shared(Vs);
    const int lrow  = (lane & 7) + ((lane >> 3) & 1) * 8;
    const int lkof  = (lane >> 4) * 8;
    const int tkrow = (lane & 7) + (lane >> 4) * 8;
    const int tncol = ((lane >> 3) & 1) * 8;

    float sacc[32][4];
    #pragma unroll
    for (int nt = 0; nt < 32; nt++)
        #pragma unroll
        for (int r = 0; r < 4; r++) sacc[nt][r] = 0.f;

    #pragma unroll
    for (int kt = 0; kt < 4; kt++) {
        unsigned af[4];
        ldsm_x4(af, Qu + (uint32_t)(((wid * 16 + lrow) * 72 + kt * 16 + lkof) * 2));
        #pragma unroll
        for (int ntp = 0; ntp < 16; ntp++) {
            unsigned r[4];
            ldsm_x4(r, Ku + (uint32_t)(((ntp * 16 + lrow) * 72 + kt * 16 + lkof) * 2));
            unsigned b0[2] = {r[0], r[2]}, b1[2] = {r[1], r[3]};
            mma_f16(sacc[2 * ntp],     af, b0);
            mma_f16(sacc[2 * ntp + 1], af, b1);
        }
    }

    const int qrow = q0 + wid * 16 + g;
    const __half* ig  = interT + ((long)bh * N_ + qrow) * N_;
    const __half* ig8 = ig + 8L * N_;
    const bool qm0 = qmsk[wid * 16 + g]     != 0.f;
    const bool qm1 = qmsk[wid * 16 + g + 8] != 0.f;

    float mx0 = -3.0e38f, mx1 = -3.0e38f;
    #pragma unroll
    for (int nt = 0; nt < 32; nt++) {
        int col = nt * 8 + 2 * tg;
        float a0 = kadd[col], a1 = kadd[col + 1];
        float2 i0 = __half22float2(*(const __half2*)(ig  + col));
        float2 i1 = __half22float2(*(const __half2*)(ig8 + col));
        float v0 = fmaf(sacc[nt][0], 0.125f, i0.x) + (qm0 ? a0 : -1e9f);
        float v1 = fmaf(sacc[nt][1], 0.125f, i0.y) + (qm0 ? a1 : -1e9f);
        float v2 = fmaf(sacc[nt][2], 0.125f, i1.x) + (qm1 ? a0 : -1e9f);
        float v3 = fmaf(sacc[nt][3], 0.125f, i1.y) + (qm1 ? a1 : -1e9f);
        sacc[nt][0] = v0; sacc[nt][1] = v1; sacc[nt][2] = v2; sacc[nt][3] = v3;
        mx0 = fmaxf(mx0, fmaxf(v0, v1));
        mx1 = fmaxf(mx1, fmaxf(v2, v3));
    }
    #pragma unroll
    for (int o = 1; o <= 2; o <<= 1) {
        mx0 = fmaxf(mx0, __shfl_xor_sync(0xffffffffu, mx0, o));
        mx1 = fmaxf(mx1, __shfl_xor_sync(0xffffffffu, mx1, o));
    }
    float s0 = 0.f, s1 = 0.f;
    #pragma unroll
    for (int nt = 0; nt < 32; nt++) {
        float e0 = __expf(sacc[nt][0] - mx0), e1 = __expf(sacc[nt][1] - mx0);
        float e2 = __expf(sacc[nt][2] - mx1), e3 = __expf(sacc[nt][3] - mx1);
        sacc[nt][0] = e0; sacc[nt][1] = e1; sacc[nt][2] = e2; sacc[nt][3] = e3;
        s0 += e0 + e1; s1 += e2 + e3;
    }
    #pragma unroll
    for (int o = 1; o <= 2; o <<= 1) {
        s0 += __shfl_xor_sync(0xffffffffu, s0, o);
        s1 += __shfl_xor_sync(0xffffffffu, s1, o);
    }

    float oacc[8][4];
    #pragma unroll
    for (int nt = 0; nt < 8; nt++)
        #pragma unroll
        for (int r = 0; r < 4; r++) oacc[nt][r] = 0.f;

    #pragma unroll
    for (int kt = 0; kt < 16; kt++) {
        unsigned ph[4];
        ph[0] = pk2(sacc[2 * kt][0],     sacc[2 * kt][1]);
        ph[1] = pk2(sacc[2 * kt][2],     sacc[2 * kt][3]);
        ph[2] = pk2(sacc[2 * kt + 1][0], sacc[2 * kt + 1][1]);
        ph[3] = pk2(sacc[2 * kt + 1][2], sacc[2 * kt + 1][3]);
        #pragma unroll
        for (int ntp = 0; ntp < 4; ntp++) {
            unsigned r[4];
            ldsm_x4t(r, Vu + (uint32_t)(((kt * 16 + tkrow) * 72 + ntp * 16 + tncol) * 2));
            unsigned b0[2] = {r[0], r[2]}, b1[2] = {r[1], r[3]};
            mma_f16(oacc[2 * ntp],     ph, b0);
            mma_f16(oacc[2 * ntp + 1], ph, b1);
        }
    }

    float inv0 = 1.f / s0, inv1 = 1.f / s1;
    __half* aob = ao + ((long)b * N_ + qrow) * D_ + h * DH_;
    #pragma unroll
    for (int nt = 0; nt < 8; nt++) {
        int col = nt * 8 + 2 * tg;
        __half2 v0 = __floats2half2_rn(oacc[nt][0] * inv0, oacc[nt][1] * inv0);
        __half2 v1 = __floats2half2_rn(oacc[nt][2] * inv1, oacc[nt][3] * inv1);
        *(__half2*)(aob + col) = v0;
        *(__half2*)(aob + 8L * D_ + col) = v1;
    }
}

// ---------------- fp16 GEMM: BM=256 BN=128 BK=64, 512 thr, 4-stage mbarrier ring ----------------
#define GSTG 4
#define A_ST 18432
#define B_ST 9216
#define AB_OFF (GSTG * A_ST)
#define HSMEM_BYTES ((GSTG * (A_ST + B_ST)) * 2)   // 221184 B

template<int TRANSB, int CHK>
__global__ void __launch_bounds__(512, 1) gemm_h(
    const __half* __restrict__ A, const __half* __restrict__ Bm, void* __restrict__ Cv,
    int M, int Nn, int K, int lda, int ldb, int ldc,
    int zdiv, long sA1, long sA2, long sB1, long sB2, long sC1, long sC2,
    const float* __restrict__ bias, const float* __restrict__ res, int ldr,
    long sR1, long sR2, int act, int cmode)
{
    extern __shared__ __half dynh[];
    __shared__ __align__(8) unsigned long long mbars[2 * GSTG];
    const uint32_t dyn_u = (uint32_t)__cvta_generic_to_shared(dynh);
    const uint32_t mb_u  = (uint32_t)__cvta_generic_to_shared(mbars);

    int z = blockIdx.z;
    long z1 = z / zdiv, z2 = z % zdiv;
    A  += z1 * sA1 + z2 * sA2;
    Bm += z1 * sB1 + z2 * sB2;
    long coff = z1 * sC1 + z2 * sC2;
    if (res) res += z1 * sR1 + z2 * sR2;

    const int tid  = threadIdx.x;
    const int wid  = tid >> 5, lane = tid & 31;
    const int wM   = wid >> 2, wN = wid & 3;
    const int g    = lane >> 2, tg = lane & 3;
    const int m0   = blockIdx.y * 256, n0 = blockIdx.x * 128;

    if (tid == 0) {
        #pragma unroll
        for (int s = 0; s < GSTG; s++) {
            mbar_init(mb_u + s * 8, 512);
            mbar_init(mb_u + 32 + s * 8, 512);
        }
    }
    __syncthreads();

    float acc[4][4][4];
    #pragma unroll
    for (int i = 0; i < 4; i++)
        #pragma unroll
        for (int j = 0; j < 4; j++)
            #pragma unroll
            for (int r = 0; r < 4; r++) acc[i][j][r] = 0.f;

    auto load_stage = [&](int buf, int k0) {
        #pragma unroll
        for (int i = 0; i < 4; i++) {
            int c = tid + i * 512;
            int row = c >> 3, col = (c & 7) << 3;
            if (CHK) {
                bool p = (m0 + row) < M;
                const __half* gp = p ? (A + (long)(m0 + row) * lda + k0 + col) : A;
                cp16(dynh + buf * A_ST + row * 72 + col, gp, p);
            } else {
                cp16u(dynh + buf * A_ST + row * 72 + col,
                      A + (long)(m0 + row) * lda + k0 + col);
            }
        }
        if (TRANSB) {
            #pragma unroll
            for (int i = 0; i < 2; i++) {
                int c = tid + i * 512;
                int row = c >> 3, col = (c & 7) << 3;
                if (CHK) {
                    bool p = (n0 + row) < Nn;
                    const __half* gp = p ? (Bm + (long)(n0 + row) * ldb + k0 + col) : Bm;
                    cp16(dynh + AB_OFF + buf * B_ST + row * 72 + col, gp, p);
                } else {
                    cp16u(dynh + AB_OFF + buf * B_ST + row * 72 + col,
                          Bm + (long)(n0 + row) * ldb + k0 + col);
                }
            }
        } else {
            #pragma unroll
            for (int i = 0; i < 2; i++) {
                int c = tid + i * 512;
                int row = c >> 4, col = (c & 15) << 3;
                if (CHK) {
                    bool p = (n0 + col) < Nn;
                    const __half* gp = p ? (Bm + (long)(k0 + row) * ldb + n0 + col) : Bm;
                    cp16(dynh + AB_OFF + buf * B_ST + row * 136 + col, gp, p);
                } else {
                    cp16u(dynh + AB_OFF + buf * B_ST + row * 136 + col,
                          Bm + (long)(k0 + row) * ldb + n0 + col);
                }
            }
        }
    };

    const int lrow = (lane & 7) + ((lane >> 3) & 1) * 8;
    const int lkof = (lane >> 4) * 8;
    const int tkrow = (lane & 7) + (lane >> 4) * 8;
    const int tncol = ((lane >> 3) & 1) * 8;

    auto compute = [&](int buf) {
        const uint32_t As = dyn_u + (uint32_t)(buf * A_ST * 2);
        const uint32_t Bs = dyn_u + (uint32_t)((AB_OFF + buf * B_ST) * 2);
        #pragma unroll
        for (int ks = 0; ks < 64; ks += 16) {
            unsigned af[4][4], bf[4][2];
            #pragma unroll
            for (int mt = 0; mt < 4; mt++)
                ldsm_x4(af[mt],
                        As + (uint32_t)(((wM * 64 + mt * 16 + lrow) * 72 + ks + lkof) * 2));
            #pragma unroll
            for (int ntp = 0; ntp < 2; ntp++) {
                unsigned r[4];
                if (TRANSB) {
                    ldsm_x4(r, Bs + (uint32_t)(((wN * 32 + ntp * 16 + lrow) * 72
                                               + ks + lkof) * 2));
                } else {
                    ldsm_x4t(r, Bs + (uint32_t)(((ks + tkrow) * 136
                                                + wN * 32 + ntp * 16 + tncol) * 2));
                }
                bf[2 * ntp][0] = r[0]; bf[2 * ntp + 1][0] = r[1];
                bf[2 * ntp][1] = r[2]; bf[2 * ntp + 1][1] = r[3];
            }
            #pragma unroll
            for (int mt = 0; mt < 4; mt++)
                #pragma unroll
                for (int nt = 0; nt < 4; nt++)
                    mma_f16(acc[mt][nt], af[mt], bf[nt]);
        }
    };

    const int KT = K >> 6;
    #pragma unroll
    for (int s = 0; s < GSTG - 1; s++) {
        load_stage(s, s * 64);
        cpasync_mbar_arrive(mb_u + s * 8);
    }
    for (int kt = 0; kt < KT; kt++) {
        int b = kt & (GSTG - 1);
        mbar_wait(mb_u + b * 8, (kt >> 2) & 1);
        compute(b);
        mbar_arrive(mb_u + 32 + b * 8);
        int pf = kt + GSTG - 1;
        if (pf < KT) {
            int pb = pf & (GSTG - 1);
            if (pf >= GSTG)
                mbar_wait(mb_u + 32 + pb * 8, ((pf >> 2) - 1) & 1);
            load_stage(pb, pf * 64);
            cpasync_mbar_arrive(mb_u + pb * 8);
        }
    }

    #pragma unroll
    for (int mt = 0; mt < 4; mt++) {
        #pragma unroll
        for (int nt = 0; nt < 4; nt++) {
            int m = m0 + wM * 64 + mt * 16 + g;
            int n = n0 + wN * 32 + nt * 8 + tg * 2;
            if (CHK && n >= Nn) continue;
            float bx = 0.f, by = 0.f;
            if (bias) { bx = bias[n]; by = bias[n + 1]; }
            #pragma unroll
            for (int half = 0; half < 2; half++) {
                int mm = m + half * 8;
                if (CHK && mm >= M) continue;
                float2 v = make_float2(acc[mt][nt][half * 2], acc[mt][nt][half * 2 + 1]);
                if (bias) { v.x += bx; v.y += by; }
                if (act) {
                    v.x = 0.5f * v.x * (1.f + erff(v.x * 0.70710678118654752f));
                    v.y = 0.5f * v.y * (1.f + erff(v.y * 0.70710678118654752f));
                }
                if (res) {
                    float2 r = *(const float2*)(res + (long)mm * ldr + n);
                    v.x += r.x; v.y += r.y;
                }
                if (cmode) {
                    __half2 hv = __floats2half2_rn(v.x, v.y);
                    *(__half2*)((__half*)Cv + coff + (long)mm * ldc + n) = hv;
                } else {
                    *(float2*)((float*)Cv + coff + (long)mm * ldc + n) = v;
                }
            }
        }
    }
}

// ---------------- class attention core ----------------
__global__ void cattn_kernel(const float* __restrict__ qh, const float* __restrict__ khvh,
                             __half* __restrict__ co, const void* __restrict__ mask) {
    int z = blockIdx.x;
    int b = z / H_, h = z % H_;
    int tid = threadIdx.x;
    __shared__ float a[NTOK_];
    __shared__ float red[4];
    const float* qv = qh + (long)b * D_ + h * DH_;
    float lmax = -3.0e38f;
    for (int sidx = tid; sidx < NTOK_; sidx += 128) {
        const float* kv = khvh + ((long)(b * NTOK_ + sidx)) * KVW_ + h * DH_;
        float sc = 0.f;
        #pragma unroll
        for (int d = 0; d < DH_; d++) sc += qv[d] * kv[d];
        sc = sc * 0.125f + ((sidx == 0 || mget(mask, b * N_ + sidx - 1)) ? 0.f : -1e9f);
        a[sidx] = sc;
        lmax = fmaxf(lmax, sc);
    }
    #pragma unroll
    for (int off = 16; off; off >>= 1) lmax = fmaxf(lmax, __shfl_xor_sync(0xffffffffu, lmax, off));
    if ((tid & 31) == 0) red[tid >> 5] = lmax;
    __syncthreads();
    float m = fmaxf(fmaxf(red[0], red[1]), fmaxf(red[2], red[3]));
    __syncthreads();
    float lsum = 0.f;
    for (int sidx = tid; sidx < NTOK_; sidx += 128) {
        float e = __expf(a[sidx] - m);
        a[sidx] = e;
        lsum += e;
    }
    #pragma unroll
    for (int off = 16; off; off >>= 1) lsum += __shfl_xor_sync(0xffffffffu, lsum, off);
    if ((tid & 31) == 0) red[tid >> 5] = lsum;
    __syncthreads();
    float inv = 1.f / (red[0] + red[1] + red[2] + red[3]);
    if (tid < DH_) {
        float o = 0.f;
        for (int sidx = 0; sidx < NTOK_; sidx++)
            o += a[sidx] * khvh[((long)(b * NTOK_ + sidx)) * KVW_ + 512 + h * DH_ + tid];
        co[(long)b * D_ + h * DH_ + tid] = __float2half(o * inv);
    }
}

// ---------------- host-side launch helpers ----------------
static void launch_gemm(const __half* A, const __half* Bm, void* C,
                        int M, int Nn, int K, int lda, int ldb, int ldc,
                        const float* bias, const float* res, int ldr, int act, int cmode,
                        int nz, int zdiv,
                        long sA1, long sA2, long sB1, long sB2, long sC1, long sC2,
                        long sR1, long sR2, bool transb) {
    dim3 grid((Nn + 127) / 128, (M + 255) / 256, nz);
    bool exact = (M % 256 == 0) && (Nn % 128 == 0);
    if (transb) {
        if (exact)
            gemm_h<1,0><<<grid, 512, HSMEM_BYTES>>>(A, Bm, C, M, Nn, K, lda, ldb, ldc,
                zdiv, sA1, sA2, sB1, sB2, sC1, sC2, bias, res, ldr, sR1, sR2, act, cmode);
        else
            gemm_h<1,1><<<grid, 512, HSMEM_BYTES>>>(A, Bm, C, M, Nn, K, lda, ldb, ldc,
                zdiv, sA1, sA2, sB1, sB2, sC1, sC2, bias, res, ldr, sR1, sR2, act, cmode);
    } else {
        if (exact)
            gemm_h<0,0><<<grid, 512, HSMEM_BYTES>>>(A, Bm, C, M, Nn, K, lda, ldb, ldc,
                zdiv, sA1, sA2, sB1, sB2, sC1, sC2, bias, res, ldr, sR1, sR2, act, cmode);
        else
            gemm_h<0,1><<<grid, 512, HSMEM_BYTES>>>(A, Bm, C, M, Nn, K, lda, ldb, ldc,
                zdiv, sA1, sA2, sB1, sB2, sC1, sC2, bias, res, ldr, sR1, sR2, act, cmode);
    }
}

static void launch_gemm_simple(const __half* A, const __half* Bm, void* C,
                               int M, int Nn, int K, int lda, int ldb, int ldc,
                               const float* bias, const float* res, int ldr,
                               int act, int cmode) {
    launch_gemm(A, Bm, C, M, Nn, K, lda, ldb, ldc, bias, res, ldr, act, cmode,
                1, 1, 0, 0, 0, 0, 0, 0, 0, 0, true);
}

extern "C" void kernel_launch(void* const* d_in, const int* in_sizes, int n_in,
                              void* d_out, int out_size) {
    const float* x       = (const float*)d_in[0];
    const float* inter   = (const float*)d_in[1];
    const float* ctok    = (const float*)d_in[2];
    const float* p_ln1_g = (const float*)d_in[3];
    const float* p_ln1_b = (const float*)d_in[4];
    const float* p_wq    = (const float*)d_in[5];
    const float* p_wk    = (const float*)d_in[6];
    const float* p_wv    = (const float*)d_in[7];
    const float* p_wo    = (const float*)d_in[8];
    const float* p_ln2_g = (const float*)d_in[9];
    const float* p_ln2_b = (const float*)d_in[10];
    const float* p_w1    = (const float*)d_in[11];
    const float* p_b1    = (const float*)d_in[12];
    const float* p_w2    = (const float*)d_in[13];
    const float* p_b2    = (const float*)d_in[14];
    const float* c_ln1_g = (const float*)d_in[15];
    const float* c_ln1_b = (const float*)d_in[16];
    const float* c_qk    = (const float*)d_in[17];
    const float* c_qb    = (const float*)d_in[18];
    const float* c_kk    = (const float*)d_in[19];
    const float* c_kb    = (const float*)d_in[20];
    const float* c_vk    = (const float*)d_in[21];
    const float* c_vb    = (const float*)d_in[22];
    const float* c_ok    = (const float*)d_in[23];
    const float* c_ob    = (const float*)d_in[24];
    const float* c_ln2_g = (const float*)d_in[25];
    const float* c_ln2_b = (const float*)d_in[26];
    const float* c_w1    = (const float*)d_in[27];
    const float* c_b1    = (const float*)d_in[28];
    const float* c_w2    = (const float*)d_in[29];
    const float* c_b2    = (const float*)d_in[30];
    const void*  mask    = d_in[31];

    cudaFuncSetAttribute(gemm_h<0,0>, cudaFuncAttributeMaxDynamicSharedMemorySize, HSMEM_BYTES);
    cudaFuncSetAttribute(gemm_h<0,1>, cudaFuncAttributeMaxDynamicSharedMemorySize, HSMEM_BYTES);
    cudaFuncSetAttribute(gemm_h<1,0>, cudaFuncAttributeMaxDynamicSharedMemorySize, HSMEM_BYTES);
    cudaFuncSetAttribute(gemm_h<1,1>, cudaFuncAttributeMaxDynamicSharedMemorySize, HSMEM_BYTES);
    cudaFuncSetAttribute(fused_attn, cudaFuncAttributeMaxDynamicSharedMemorySize, FA_SMEM);

    float *h, *khvh, *qh, *query, *ckvb;
    __half *hn, *qkv, *ao, *interT, *t, *cn, *co, *queryh, *cfn, *cff;
    __half *wqkvT, *woT, *w1T, *w2T, *cqkT, *ckvT, *cokT, *cw1T, *cw2T;
    cudaGetSymbolAddress((void**)&h,     g_h);
    cudaGetSymbolAddress((void**)&hn,    g_hn);
    cudaGetSymbolAddress((void**)&qkv,   g_qkv);
    cudaGetSymbolAddress((void**)&ao,    g_ao);
    cudaGetSymbolAddress((void**)&interT,g_interT);
    cudaGetSymbolAddress((void**)&t,     g_t);
    cudaGetSymbolAddress((void**)&cn,    g_cn);
    cudaGetSymbolAddress((void**)&khvh,  g_khvh);
    cudaGetSymbolAddress((void**)&qh,    g_qh);
    cudaGetSymbolAddress((void**)&co,    g_co);
    cudaGetSymbolAddress((void**)&query, g_query);
    cudaGetSymbolAddress((void**)&queryh,g_queryh);
    cudaGetSymbolAddress((void**)&cfn,   g_cfn);
    cudaGetSymbolAddress((void**)&cff,   g_cff);
    cudaGetSymbolAddress((void**)&ckvb,  g_ckvb);
    cudaGetSymbolAddress((void**)&wqkvT, g_wqkvT);
    cudaGetSymbolAddress((void**)&woT,   g_woT);
    cudaGetSymbolAddress((void**)&w1T,   g_w1T);
    cudaGetSymbolAddress((void**)&w2T,   g_w2T);
    cudaGetSymbolAddress((void**)&cqkT,  g_cqkT);
    cudaGetSymbolAddress((void**)&ckvT,  g_ckvT);
    cudaGetSymbolAddress((void**)&cokT,  g_cokT);
    cudaGetSymbolAddress((void**)&cw1T,  g_cw1T);
    cudaGetSymbolAddress((void**)&cw2T,  g_cw2T);

    // prep
    {
        WTable w;
        auto set = [&](int i, const float* s, __half* d, int K, int N, int layers, long dStride) {
            w.src[i] = s; w.dst[i] = d; w.K[i] = K; w.N[i] = N;
            w.sS[i] = (long)K * N;
            w.dS[i] = dStride;
            int tiles = (K / 64) * (N / 64) * layers;
            w.base[i + 1] = w.base[i] + tiles;
        };
        w.base[0] = 0;
        set(0,  p_wq, wqkvT + 0L * D_,    D_, D_, L_,  (long)QKVW_ * D_);
        set(1,  p_wk, wqkvT + 512L * D_,  D_, D_, L_,  (long)QKVW_ * D_);
        set(2,  p_wv, wqkvT + 1024L * D_, D_, D_, L_,  (long)QKVW_ * D_);
        set(3,  p_wo, woT,  D_, D_, L_,  (long)D_ * D_);
        set(4,  p_w1, w1T,  D_, F_, L_,  (long)D_ * F_);
        set(5,  p_w2, w2T,  F_, D_, L_,  (long)F_ * D_);
        set(6,  c_qk, cqkT, D_, D_, LC_, (long)D_ * D_);
        set(7,  c_kk, ckvT + 0L * D_,   D_, D_, LC_, (long)KVW_ * D_);
        set(8,  c_vk, ckvT + 512L * D_, D_, D_, LC_, (long)KVW_ * D_);
        set(9,  c_ok, cokT, D_, D_, LC_, (long)D_ * D_);
        set(10, c_w1, cw1T, D_, F_, LC_, (long)D_ * F_);
        transpose_all<<<w.base[NWT], dim3(32, 8)>>>(w);
    }
    {
        WTable w2t;
        w2t.base[0] = 0;
        for (int i = 0; i < NWT; i++) { w2t.src[i] = c_w2; w2t.dst[i] = cw2T;
            w2t.K[i] = F_; w2t.N[i] = D_; w2t.sS[i] = (long)F_ * D_; w2t.dS[i] = (long)D_ * F_;
            w2t.base[i + 1] = (i == 0) ? (F_/64)*(D_/64)*LC_ : w2t.base[i]; }
        transpose_all<<<(F_/64)*(D_/64)*LC_, dim3(32, 8)>>>(w2t);
    }
    ckvb_kernel<<<(LC_*KVW_ + 255) / 256, 256>>>(c_kb, c_vb);

    // -------- particle transformer layers --------
    for (int l = 0; l < L_; l++) {
        const float* hin = (l == 0) ? x : h;
        ln_kernel<<<B_*N_/8, 256>>>(hin, hn, p_ln1_g + (long)l * D_, p_ln1_b + (long)l * D_);

        // fused QKV -> qkv[M, 1536] (half)
        launch_gemm_simple(hn, wqkvT + (long)l * QKVW_ * D_, qkv,
                           B_*N_, QKVW_, D_, D_, D_, QKVW_, nullptr, nullptr, 0, 0, 1);

        if (l == 0) {
            transpose_inter<<<B_*N_, 256>>>(inter, interT);
            detect_mask_kernel<<<1, 1>>>((const unsigned int*)mask);
        }

        // fused score+softmax+AV -> ao (half)
        fused_attn<<<dim3(2, B_*H_), 256, FA_SMEM>>>(qkv, interT, mask, ao);

        // h = hin + ao @ Wo
        launch_gemm_simple(ao, woT + (long)l * D_ * D_, h,
                           B_*N_, D_, D_, D_, D_, D_, nullptr, hin, D_, 0, 0);

        // FFN
        ln_kernel<<<B_*N_/8, 256>>>(h, hn, p_ln2_g + (long)l * D_, p_ln2_b + (long)l * D_);
        launch_gemm_simple(hn, w1T + (long)l * F_ * D_, t,
                           B_*N_, F_, D_, D_, D_, F_, p_b1 + (long)l * F_, nullptr, 0, 1, 1);
        launch_gemm_simple(t, w2T + (long)l * D_ * F_, h,
                           B_*N_, D_, F_, F_, F_, D_, p_b2 + (long)l * D_, h, D_, 0, 0);
    }

    // -------- class attention layers --------
    bcast_token_kernel<<<(B_*D_ + 255) / 256, 256>>>(ctok);
    for (int l = 0; l < LC_; l++) {
        ln_cat_kernel<<<B_*NTOK_/8, 256>>>(query, h, cn,
                                           c_ln1_g + (long)l * D_, c_ln1_b + (long)l * D_);
        f2h_kernel<<<(B_*D_ + 255) / 256, 256>>>(query, queryh, B_*D_);
        launch_gemm_simple(queryh, cqkT + (long)l * D_ * D_, qh, B_, D_, D_, D_, D_, D_,
                           c_qb + (long)l * D_, nullptr, 0, 0, 0);
        launch_gemm_simple(cn, ckvT + (long)l * KVW_ * D_, khvh, B_*NTOK_, KVW_, D_,
                           D_, D_, KVW_, ckvb + (long)l * KVW_, nullptr, 0, 0, 0);

        cattn_kernel<<<B_*H_, 128>>>(qh, khvh, co, mask);

        launch_gemm_simple(co, cokT + (long)l * D_ * D_, query, B_, D_, D_, D_, D_, D_,
                           c_ob + (long)l * D_, query, D_, 0, 0);

        ln_small_kernel<<<(B_ + 7) / 8, 256>>>(query, cfn,
                                               c_ln2_g + (long)l * D_, c_ln2_b + (long)l * D_);
        launch_gemm_simple(cfn, cw1T + (long)l * F_ * D_, cff, B_, F_, D_, D_, D_, F_,
                           c_b1 + (long)l * F_, nullptr, 0, 1, 1);
        launch_gemm_simple(cff, cw2T + (long)l * D_ * F_, query, B_, D_, F_, F_, F_, D_,
                           c_b2 + (long)l * D_, query, D_, 0, 0);
    }

    copy_kernel<<<(B_*D_ + 255) / 256, 256>>>(query, (float*)d_out, B_*D_);
}

// round 16
// speedup vs baseline: 1.0790x; 1.0576x over previous
#include <cuda_runtime.h>
#include <cuda_fp16.h>
#include <math.h>
#include <stdint.h>

#define B_ 32
#define N_ 256
#define D_ 512
#define H_ 8
#define DH_ 64
#define F_ 2048
#define L_ 8
#define LC_ 2
#define NTOK_ 257
#define QKVW_ 1536
#define KVW_ 1024

// ---------------- scratch (device globals; no allocation allowed) ----------------
static __device__ float  g_h  [B_*N_*D_];
static __device__ __half g_hn [B_*N_*D_];
static __device__ __half g_qkv[B_*N_*QKVW_];
static __device__ __half g_ao [B_*N_*D_];
static __device__ __half g_interT[B_*H_*N_*N_];
static __device__ __half g_t  [B_*N_*F_];
static __device__ __half g_cn [B_*NTOK_*D_];
static __device__ float  g_khvh[B_*NTOK_*KVW_];
static __device__ float  g_qh [B_*D_];
static __device__ __half g_co [B_*D_];
static __device__ float  g_query[B_*D_];
static __device__ __half g_queryh[B_*D_];
static __device__ __half g_cfn[B_*D_];
static __device__ __half g_cff[B_*F_];
static __device__ float  g_ckvb[LC_*KVW_];
static __device__ int    g_mask_mode;

// transposed fp16 weights: [N][K] row-major
static __device__ __half g_wqkvT[L_*QKVW_*D_];
static __device__ __half g_woT [L_*D_*D_];
static __device__ __half g_w1T [L_*F_*D_];
static __device__ __half g_w2T [L_*D_*F_];
static __device__ __half g_cqkT[LC_*D_*D_];
static __device__ __half g_ckvT[LC_*KVW_*D_];
static __device__ __half g_cokT[LC_*D_*D_];
static __device__ __half g_cw1T[LC_*F_*D_];
static __device__ __half g_cw2T[LC_*D_*F_];

__device__ __forceinline__ bool mget(const void* m, int idx) {
    int mode = g_mask_mode;
    if (mode == 1) return ((const unsigned char*)m)[idx] != 0;
    if (mode == 2) return ((const float*)m)[idx] != 0.0f;
    return ((const int*)m)[idx] != 0;
}

// ---------------- tiny utility kernels ----------------
__global__ void copy_kernel(const float* __restrict__ src, float* __restrict__ dst, int n) {
    int i = blockIdx.x * 256 + threadIdx.x;
    if (i < n) dst[i] = src[i];
}

__global__ void f2h_kernel(const float* __restrict__ src, __half* __restrict__ dst, int n) {
    int i = blockIdx.x * 256 + threadIdx.x;
    if (i < n) dst[i] = __float2half(src[i]);
}

__global__ void bcast_token_kernel(const float* __restrict__ tok) {
    int i = blockIdx.x * 256 + threadIdx.x;
    if (i < B_*D_) g_query[i] = tok[i % D_];
}

// ---------------- ONE prep launch: weight transposes + interT + ckvb + mask detect ----------
#define NWT 12
struct WTable {
    const float* src[NWT];
    __half*      dst[NWT];
    int          K[NWT], N[NWT];
    long         sS[NWT], dS[NWT];
    int          base[NWT + 1];
};

__global__ void prep_all(WTable w, const float* __restrict__ inter, __half* __restrict__ interT,
                         const unsigned int* __restrict__ mask,
                         const float* __restrict__ kb, const float* __restrict__ vb) {
    int bx = blockIdx.x;
    int t = threadIdx.y * 32 + threadIdx.x;   // 0..255
    if (bx == 0 && t == 0) {
        unsigned int v = mask[0];
        int mode = 0;
        if (v == 0x01010101u) mode = 1;
        else if (v == 0x3F800000u) mode = 2;
        g_mask_mode = mode;
    }
    int WT = w.base[NWT];
    if (bx < WT) {
        // 64x64 weight transpose tile
        __shared__ float tile[64][65];
        int gsel = 0;
        #pragma unroll
        for (int i = 1; i < NWT; i++) if (bx >= w.base[i]) gsel = i;
        int local = bx - w.base[gsel];
        int K = w.K[gsel], N = w.N[gsel];
        int ncols = N >> 6;
        int tpl = (K >> 6) * ncols;
        int layer = local / tpl;
        int rem = local % tpl;
        int k0 = (rem / ncols) * 64, n0 = (rem % ncols) * 64;
        const float* src = w.src[gsel] + (long)layer * w.sS[gsel];
        __half* dst = w.dst[gsel] + (long)layer * w.dS[gsel];
        #pragma unroll
        for (int i = 0; i < 4; i++) {
            int r = i * 16 + (t >> 4);
            int c = (t & 15) * 4;
            float4 v = *(const float4*)(src + (long)(k0 + r) * N + n0 + c);
            tile[r][c] = v.x; tile[r][c + 1] = v.y; tile[r][c + 2] = v.z; tile[r][c + 3] = v.w;
        }
        __syncthreads();
        #pragma unroll
        for (int i = 0; i < 8; i++) {
            int n = i * 8 + (t >> 5);
            int kc = (t & 31) * 2;
            __half2 hv = __floats2half2_rn(tile[kc][n], tile[kc + 1][n]);
            *(__half2*)(dst + (long)(n0 + n) * K + k0 + kc) = hv;
        }
    } else if (bx < WT + B_*N_) {
        // inter [B,N,N,H] f32 -> interT [B,H,N,N] f16, one (b,qi) row per block
        int row = bx - WT;
        int b = row >> 8, qi = row & 255;
        int k = t;
        const float4* ip = (const float4*)(inter + ((long)row * N_ + k) * H_);
        float4 i0 = ip[0], i1 = ip[1];
        float v[8] = {i0.x, i0.y, i0.z, i0.w, i1.x, i1.y, i1.z, i1.w};
        #pragma unroll
        for (int h = 0; h < H_; h++)
            interT[((long)(b * H_ + h) * N_ + qi) * N_ + k] = __float2half(v[h]);
    } else {
        // combined class K/V bias: 8 blocks
        int i = (bx - WT - B_*N_) * 256 + t;
        if (i < LC_ * KVW_) {
            int l = i >> 10, c = i & 1023;
            g_ckvb[i] = (c < 512) ? kb[l * 512 + c] : vb[l * 512 + c - 512];
        }
    }
}

// ---------------- LayerNorm (eps = 1e-3): one WARP per row ----------------
__device__ __forceinline__ void ln_row_warp(const float* __restrict__ x, __half* __restrict__ o,
                                            const float* __restrict__ g, const float* __restrict__ bb) {
    int lane = threadIdx.x & 31;
    float4 v[4];
    #pragma unroll
    for (int i = 0; i < 4; i++)
        v[i] = *(const float4*)(x + (i * 32 + lane) * 4);
    float s = 0.f, s2 = 0.f;
    #pragma unroll
    for (int i = 0; i < 4; i++) {
        s  += v[i].x + v[i].y + v[i].z + v[i].w;
        s2 += v[i].x*v[i].x + v[i].y*v[i].y + v[i].z*v[i].z + v[i].w*v[i].w;
    }
    #pragma unroll
    for (int off = 16; off; off >>= 1) {
        s  += __shfl_xor_sync(0xffffffffu, s,  off);
        s2 += __shfl_xor_sync(0xffffffffu, s2, off);
    }
    float mean = s * (1.f / D_);
    float var  = s2 * (1.f / D_) - mean * mean;
    float r = rsqrtf(var + 1e-3f);
    #pragma unroll
    for (int i = 0; i < 4; i++) {
        int idx = (i * 32 + lane) * 4;
        float4 g4 = *(const float4*)(g + idx);
        float4 b4 = *(const float4*)(bb + idx);
        float o0 = (v[i].x - mean) * r * g4.x + b4.x;
        float o1 = (v[i].y - mean) * r * g4.y + b4.y;
        float o2 = (v[i].z - mean) * r * g4.z + b4.z;
        float o3 = (v[i].w - mean) * r * g4.w + b4.w;
        __half2 h0 = __floats2half2_rn(o0, o1);
        __half2 h1 = __floats2half2_rn(o2, o3);
        uint2 u; u.x = *(unsigned*)&h0; u.y = *(unsigned*)&h1;
        *(uint2*)(o + idx) = u;
    }
}

__global__ void ln_kernel(const float* __restrict__ in, __half* __restrict__ out,
                          const float* __restrict__ g, const float* __restrict__ b) {
    long row = blockIdx.x * 8 + (threadIdx.x >> 5);
    ln_row_warp(in + row * D_, out + row * D_, g, b);
}

__global__ void ln_cat_kernel(const float* __restrict__ query, const float* __restrict__ h,
                              __half* __restrict__ out,
                              const float* __restrict__ g, const float* __restrict__ b) {
    int row = blockIdx.x * 8 + (threadIdx.x >> 5);
    int bb = row / NTOK_, sidx = row % NTOK_;
    const float* x = (sidx == 0) ? (query + (long)bb * D_)
                                 : (h + ((long)(bb * N_) + sidx - 1) * D_);
    ln_row_warp(x, out + (long)row * D_, g, b);
}

__global__ void ln_small_kernel(const float* __restrict__ in, __half* __restrict__ out,
                                const float* __restrict__ g, const float* __restrict__ b) {
    long row = blockIdx.x * 8 + (threadIdx.x >> 5);
    if (row < B_) ln_row_warp(in + row * D_, out + row * D_, g, b);
}

// ---------------- cp.async helpers ----------------
__device__ __forceinline__ void cp16(void* smem_ptr, const void* gptr, bool pred) {
    uint32_t sa = (uint32_t)__cvta_generic_to_shared(smem_ptr);
    int sz = pred ? 16 : 0;
    asm volatile("cp.async.cg.shared.global [%0], [%1], 16, %2;\n" :: "r"(sa), "l"(gptr), "r"(sz));
}
__device__ __forceinline__ void cp16u(void* smem_ptr, const void* gptr) {
    uint32_t sa = (uint32_t)__cvta_generic_to_shared(smem_ptr);
    asm volatile("cp.async.cg.shared.global [%0], [%1], 16;\n" :: "r"(sa), "l"(gptr));
}
__device__ __forceinline__ void cp_commit() {
    asm volatile("cp.async.commit_group;\n" ::: "memory");
}
template<int NN>
__device__ __forceinline__ void cp_wait() {
    asm volatile("cp.async.wait_group %0;\n" :: "n"(NN) : "memory");
}

// ---------------- mbarrier helpers ----------------
__device__ __forceinline__ void mbar_init(uint32_t a, uint32_t cnt) {
    asm volatile("mbarrier.init.shared.b64 [%0], %1;" :: "r"(a), "r"(cnt) : "memory");
}
__device__ __forceinline__ void mbar_arrive(uint32_t a) {
    asm volatile("mbarrier.arrive.shared.b64 _, [%0];" :: "r"(a) : "memory");
}
__device__ __forceinline__ void cpasync_mbar_arrive(uint32_t a) {
    asm volatile("cp.async.mbarrier.arrive.noinc.shared.b64 [%0];" :: "r"(a) : "memory");
}
__device__ __forceinline__ void mbar_wait(uint32_t a, uint32_t parity) {
    uint32_t done = 0;
    while (!done) {
        asm volatile("{\n\t.reg .pred p;\n\t"
            "mbarrier.try_wait.parity.acquire.cta.shared::cta.b64 p, [%1], %2, 0x989680;\n\t"
            "selp.b32 %0, 1, 0, p;\n\t}" : "=r"(done) : "r"(a), "r"(parity) : "memory");
    }
}

// ---------------- ldmatrix helpers ----------------
__device__ __forceinline__ void ldsm_x4(unsigned r[4], uint32_t addr) {
    asm volatile("ldmatrix.sync.aligned.m8n8.x4.shared.b16 {%0,%1,%2,%3}, [%4];"
        : "=r"(r[0]), "=r"(r[1]), "=r"(r[2]), "=r"(r[3]) : "r"(addr));
}
__device__ __forceinline__ void ldsm_x4t(unsigned r[4], uint32_t addr) {
    asm volatile("ldmatrix.sync.aligned.m8n8.x4.trans.shared.b16 {%0,%1,%2,%3}, [%4];"
        : "=r"(r[0]), "=r"(r[1]), "=r"(r[2]), "=r"(r[3]) : "r"(addr));
}

// ---------------- fp16 tensor-core mma ----------------
__device__ __forceinline__ void mma_f16(float c[4], const unsigned a[4], const unsigned b[2]) {
    asm volatile(
        "mma.sync.aligned.m16n8k16.row.col.f32.f16.f16.f32 "
        "{%0,%1,%2,%3}, {%4,%5,%6,%7}, {%8,%9}, {%0,%1,%2,%3};\n"
        : "+f"(c[0]), "+f"(c[1]), "+f"(c[2]), "+f"(c[3])
        : "r"(a[0]), "r"(a[1]), "r"(a[2]), "r"(a[3]), "r"(b[0]), "r"(b[1]));
}

__device__ __forceinline__ unsigned pk2(float a, float b) {
    __half2 x = __floats2half2_rn(a, b);
    return *(unsigned*)&x;
}

// ---------------- fused attention ----------------
#define FA_SMEM ((128*72 + 2*256*72) * 2 + 256*4 + 128*4)

__global__ void __launch_bounds__(256, 1) fused_attn(
    const __half* __restrict__ qkv, const __half* __restrict__ interT,
    const void* __restrict__ mask, __half* __restrict__ ao)
{
    extern __shared__ __half sm[];
    __half* Qs = sm;
    __half* Ks = sm + 128*72;
    __half* Vs = sm + 128*72 + 256*72;
    float* kadd = (float*)(sm + 128*72 + 2*256*72);
    float* qmsk = kadd + 256;

    const int q0 = blockIdx.x * 128;
    const int bh = blockIdx.y;
    const int b = bh >> 3, h = bh & 7;
    const int tid = threadIdx.x, wid = tid >> 5, lane = tid & 31;
    const int g = lane >> 2, tg = lane & 3;

    const __half* qbase = qkv + (long)b * N_ * QKVW_ + h * DH_;

    #pragma unroll
    for (int i = 0; i < 4; i++) {
        int c = tid + i * 256;
        int row = c >> 3, ch = (c & 7) * 8;
        cp16u(Qs + row * 72 + ch, qbase + (long)(q0 + row) * QKVW_ + ch);
    }
    #pragma unroll
    for (int i = 0; i < 8; i++) {
        int c = tid + i * 256;
        int row = c >> 3, ch = (c & 7) * 8;
        cp16u(Ks + row * 72 + ch, qbase + 512  + (long)row * QKVW_ + ch);
        cp16u(Vs + row * 72 + ch, qbase + 1024 + (long)row * QKVW_ + ch);
    }
    kadd[tid] = mget(mask, b * N_ + tid) ? 0.f : -1e9f;
    if (tid < 128) qmsk[tid] = mget(mask, b * N_ + q0 + tid) ? 1.f : 0.f;
    cp_commit();
    cp_wait<0>();
    __syncthreads();

    const uint32_t Qu = (uint32_t)__cvta_generic_to_shared(Qs);
    const uint32_t Ku = (uint32_t)__cvta_generic_to_shared(Ks);
    const uint32_t Vu = (uint32_t)__cvta_generic_to_shared(Vs);
    const int lrow  = (lane & 7) + ((lane >> 3) & 1) * 8;
    const int lkof  = (lane >> 4) * 8;
    const int tkrow = (lane & 7) + (lane >> 4) * 8;
    const int tncol = ((lane >> 3) & 1) * 8;

    float sacc[32][4];
    #pragma unroll
    for (int nt = 0; nt < 32; nt++)
        #pragma unroll
        for (int r = 0; r < 4; r++) sacc[nt][r] = 0.f;

    #pragma unroll
    for (int kt = 0; kt < 4; kt++) {
        unsigned af[4];
        ldsm_x4(af, Qu + (uint32_t)(((wid * 16 + lrow) * 72 + kt * 16 + lkof) * 2));
        #pragma unroll
        for (int ntp = 0; ntp < 16; ntp++) {
            unsigned r[4];
            ldsm_x4(r, Ku + (uint32_t)(((ntp * 16 + lrow) * 72 + kt * 16 + lkof) * 2));
            unsigned b0[2] = {r[0], r[2]}, b1[2] = {r[1], r[3]};
            mma_f16(sacc[2 * ntp],     af, b0);
            mma_f16(sacc[2 * ntp + 1], af, b1);
        }
    }

    const int qrow = q0 + wid * 16 + g;
    const __half* ig  = interT + ((long)bh * N_ + qrow) * N_;
    const __half* ig8 = ig + 8L * N_;
    const bool qm0 = qmsk[wid * 16 + g]     != 0.f;
    const bool qm1 = qmsk[wid * 16 + g + 8] != 0.f;

    float mx0 = -3.0e38f, mx1 = -3.0e38f;
    #pragma unroll
    for (int nt = 0; nt < 32; nt++) {
        int col = nt * 8 + 2 * tg;
        float a0 = kadd[col], a1 = kadd[col + 1];
        float2 i0 = __half22float2(*(const __half2*)(ig  + col));
        float2 i1 = __half22float2(*(const __half2*)(ig8 + col));
        float v0 = fmaf(sacc[nt][0], 0.125f, i0.x) + (qm0 ? a0 : -1e9f);
        float v1 = fmaf(sacc[nt][1], 0.125f, i0.y) + (qm0 ? a1 : -1e9f);
        float v2 = fmaf(sacc[nt][2], 0.125f, i1.x) + (qm1 ? a0 : -1e9f);
        float v3 = fmaf(sacc[nt][3], 0.125f, i1.y) + (qm1 ? a1 : -1e9f);
        sacc[nt][0] = v0; sacc[nt][1] = v1; sacc[nt][2] = v2; sacc[nt][3] = v3;
        mx0 = fmaxf(mx0, fmaxf(v0, v1));
        mx1 = fmaxf(mx1, fmaxf(v2, v3));
    }
    #pragma unroll
    for (int o = 1; o <= 2; o <<= 1) {
        mx0 = fmaxf(mx0, __shfl_xor_sync(0xffffffffu, mx0, o));
        mx1 = fmaxf(mx1, __shfl_xor_sync(0xffffffffu, mx1, o));
    }
    float s0 = 0.f, s1 = 0.f;
    #pragma unroll
    for (int nt = 0; nt < 32; nt++) {
        float e0 = __expf(sacc[nt][0] - mx0), e1 = __expf(sacc[nt][1] - mx0);
        float e2 = __expf(sacc[nt][2] - mx1), e3 = __expf(sacc[nt][3] - mx1);
        sacc[nt][0] = e0; sacc[nt][1] = e1; sacc[nt][2] = e2; sacc[nt][3] = e3;
        s0 += e0 + e1; s1 += e2 + e3;
    }
    #pragma unroll
    for (int o = 1; o <= 2; o <<= 1) {
        s0 += __shfl_xor_sync(0xffffffffu, s0, o);
        s1 += __shfl_xor_sync(0xffffffffu, s1, o);
    }

    float oacc[8][4];
    #pragma unroll
    for (int nt = 0; nt < 8; nt++)
        #pragma unroll
        for (int r = 0; r < 4; r++) oacc[nt][r] = 0.f;

    #pragma unroll
    for (int kt = 0; kt < 16; kt++) {
        unsigned ph[4];
        ph[0] = pk2(sacc[2 * kt][0],     sacc[2 * kt][1]);
        ph[1] = pk2(sacc[2 * kt][2],     sacc[2 * kt][3]);
        ph[2] = pk2(sacc[2 * kt + 1][0], sacc[2 * kt + 1][1]);
        ph[3] = pk2(sacc[2 * kt + 1][2], sacc[2 * kt + 1][3]);
        #pragma unroll
        for (int ntp = 0; ntp < 4; ntp++) {
            unsigned r[4];
            ldsm_x4t(r, Vu + (uint32_t)(((kt * 16 + tkrow) * 72 + ntp * 16 + tncol) * 2));
            unsigned b0[2] = {r[0], r[2]}, b1[2] = {r[1], r[3]};
            mma_f16(oacc[2 * ntp],     ph, b0);
            mma_f16(oacc[2 * ntp + 1], ph, b1);
        }
    }

    float inv0 = 1.f / s0, inv1 = 1.f / s1;
    __half* aob = ao + ((long)b * N_ + qrow) * D_ + h * DH_;
    #pragma unroll
    for (int nt = 0; nt < 8; nt++) {
        int col = nt * 8 + 2 * tg;
        __half2 v0 = __floats2half2_rn(oacc[nt][0] * inv0, oacc[nt][1] * inv0);
        __half2 v1 = __floats2half2_rn(oacc[nt][2] * inv1, oacc[nt][3] * inv1);
        *(__half2*)(aob + col) = v0;
        *(__half2*)(aob + 8L * D_ + col) = v1;
    }
}

// ---------------- fp16 GEMM: BM=256 BN=128 BK=64, 512 thr, 4-stage mbarrier ring ----------------
#define GSTG 4
#define A_ST 18432
#define B_ST 9216
#define AB_OFF (GSTG * A_ST)
#define HSMEM_BYTES ((GSTG * (A_ST + B_ST)) * 2)   // 221184 B

template<int TRANSB, int CHK>
__global__ void __launch_bounds__(512, 1) gemm_h(
    const __half* __restrict__ A, const __half* __restrict__ Bm, void* __restrict__ Cv,
    int M, int Nn, int K, int lda, int ldb, int ldc,
    int zdiv, long sA1, long sA2, long sB1, long sB2, long sC1, long sC2,
    const float* __restrict__ bias, const float* __restrict__ res, int ldr,
    long sR1, long sR2, int act, int cmode)
{
    extern __shared__ __half dynh[];
    __shared__ __align__(8) unsigned long long mbars[2 * GSTG];
    const uint32_t dyn_u = (uint32_t)__cvta_generic_to_shared(dynh);
    const uint32_t mb_u  = (uint32_t)__cvta_generic_to_shared(mbars);

    int z = blockIdx.z;
    long z1 = z / zdiv, z2 = z % zdiv;
    A  += z1 * sA1 + z2 * sA2;
    Bm += z1 * sB1 + z2 * sB2;
    long coff = z1 * sC1 + z2 * sC2;
    if (res) res += z1 * sR1 + z2 * sR2;

    const int tid  = threadIdx.x;
    const int wid  = tid >> 5, lane = tid & 31;
    const int wM   = wid >> 2, wN = wid & 3;
    const int g    = lane >> 2, tg = lane & 3;
    const int m0   = blockIdx.y * 256, n0 = blockIdx.x * 128;

    if (tid == 0) {
        #pragma unroll
        for (int s = 0; s < GSTG; s++) {
            mbar_init(mb_u + s * 8, 512);
            mbar_init(mb_u + 32 + s * 8, 512);
        }
    }
    __syncthreads();

    float acc[4][4][4];
    #pragma unroll
    for (int i = 0; i < 4; i++)
        #pragma unroll
        for (int j = 0; j < 4; j++)
            #pragma unroll
            for (int r = 0; r < 4; r++) acc[i][j][r] = 0.f;

    auto load_stage = [&](int buf, int k0) {
        #pragma unroll
        for (int i = 0; i < 4; i++) {
            int c = tid + i * 512;
            int row = c >> 3, col = (c & 7) << 3;
            if (CHK) {
                bool p = (m0 + row) < M;
                const __half* gp = p ? (A + (long)(m0 + row) * lda + k0 + col) : A;
                cp16(dynh + buf * A_ST + row * 72 + col, gp, p);
            } else {
                cp16u(dynh + buf * A_ST + row * 72 + col,
                      A + (long)(m0 + row) * lda + k0 + col);
            }
        }
        if (TRANSB) {
            #pragma unroll
            for (int i = 0; i < 2; i++) {
                int c = tid + i * 512;
                int row = c >> 3, col = (c & 7) << 3;
                if (CHK) {
                    bool p = (n0 + row) < Nn;
                    const __half* gp = p ? (Bm + (long)(n0 + row) * ldb + k0 + col) : Bm;
                    cp16(dynh + AB_OFF + buf * B_ST + row * 72 + col, gp, p);
                } else {
                    cp16u(dynh + AB_OFF + buf * B_ST + row * 72 + col,
                          Bm + (long)(n0 + row) * ldb + k0 + col);
                }
            }
        } else {
            #pragma unroll
            for (int i = 0; i < 2; i++) {
                int c = tid + i * 512;
                int row = c >> 4, col = (c & 15) << 3;
                if (CHK) {
                    bool p = (n0 + col) < Nn;
                    const __half* gp = p ? (Bm + (long)(k0 + row) * ldb + n0 + col) : Bm;
                    cp16(dynh + AB_OFF + buf * B_ST + row * 136 + col, gp, p);
                } else {
                    cp16u(dynh + AB_OFF + buf * B_ST + row * 136 + col,
                          Bm + (long)(k0 + row) * ldb + n0 + col);
                }
            }
        }
    };

    const int lrow = (lane & 7) + ((lane >> 3) & 1) * 8;
    const int lkof = (lane >> 4) * 8;
    const int tkrow = (lane & 7) + (lane >> 4) * 8;
    const int tncol = ((lane >> 3) & 1) * 8;

    auto compute = [&](int buf) {
        const uint32_t As = dyn_u + (uint32_t)(buf * A_ST * 2);
        const uint32_t Bs = dyn_u + (uint32_t)((AB_OFF + buf * B_ST) * 2);
        #pragma unroll
        for (int ks = 0; ks < 64; ks += 16) {
            unsigned af[4][4], bf[4][2];
            #pragma unroll
            for (int mt = 0; mt < 4; mt++)
                ldsm_x4(af[mt],
                        As + (uint32_t)(((wM * 64 + mt * 16 + lrow) * 72 + ks + lkof) * 2));
            #pragma unroll
            for (int ntp = 0; ntp < 2; ntp++) {
                unsigned r[4];
                if (TRANSB) {
                    ldsm_x4(r, Bs + (uint32_t)(((wN * 32 + ntp * 16 + lrow) * 72
                                               + ks + lkof) * 2));
                } else {
                    ldsm_x4t(r, Bs + (uint32_t)(((ks + tkrow) * 136
                                                + wN * 32 + ntp * 16 + tncol) * 2));
                }
                bf[2 * ntp][0] = r[0]; bf[2 * ntp + 1][0] = r[1];
                bf[2 * ntp][1] = r[2]; bf[2 * ntp + 1][1] = r[3];
            }
            #pragma unroll
            for (int mt = 0; mt < 4; mt++)
                #pragma unroll
                for (int nt = 0; nt < 4; nt++)
                    mma_f16(acc[mt][nt], af[mt], bf[nt]);
        }
    };

    const int KT = K >> 6;
    #pragma unroll
    for (int s = 0; s < GSTG - 1; s++) {
        load_stage(s, s * 64);
        cpasync_mbar_arrive(mb_u + s * 8);
    }
    for (int kt = 0; kt < KT; kt++) {
        int b = kt & (GSTG - 1);
        mbar_wait(mb_u + b * 8, (kt >> 2) & 1);
        compute(b);
        mbar_arrive(mb_u + 32 + b * 8);
        int pf = kt + GSTG - 1;
        if (pf < KT) {
            int pb = pf & (GSTG - 1);
            if (pf >= GSTG)
                mbar_wait(mb_u + 32 + pb * 8, ((pf >> 2) - 1) & 1);
            load_stage(pb, pf * 64);
            cpasync_mbar_arrive(mb_u + pb * 8);
        }
    }

    #pragma unroll
    for (int mt = 0; mt < 4; mt++) {
        #pragma unroll
        for (int nt = 0; nt < 4; nt++) {
            int m = m0 + wM * 64 + mt * 16 + g;
            int n = n0 + wN * 32 + nt * 8 + tg * 2;
            if (CHK && n >= Nn) continue;
            float bx = 0.f, by = 0.f;
            if (bias) { bx = bias[n]; by = bias[n + 1]; }
            #pragma unroll
            for (int half = 0; half < 2; half++) {
                int mm = m + half * 8;
                if (CHK && mm >= M) continue;
                float2 v = make_float2(acc[mt][nt][half * 2], acc[mt][nt][half * 2 + 1]);
                if (bias) { v.x += bx; v.y += by; }
                if (act) {
                    v.x = 0.5f * v.x * (1.f + erff(v.x * 0.70710678118654752f));
                    v.y = 0.5f * v.y * (1.f + erff(v.y * 0.70710678118654752f));
                }
                if (res) {
                    float2 r = *(const float2*)(res + (long)mm * ldr + n);
                    v.x += r.x; v.y += r.y;
                }
                if (cmode) {
                    __half2 hv = __floats2half2_rn(v.x, v.y);
                    *(__half2*)((__half*)Cv + coff + (long)mm * ldc + n) = hv;
                } else {
                    *(float2*)((float*)Cv + coff + (long)mm * ldc + n) = v;
                }
            }
        }
    }
}

// ---------------- small-M fp16 GEMM: M<=32, BN=128, BK=64, 256 thr, 2-stage ----------------
// A [M][K] half; B [N][K] half (transb only). C fp32 or half; bias/act/res flags.
#define S_A 2304   // 32*72
#define S_B 9216   // 128*72

__global__ void __launch_bounds__(256) gemm_s(
    const __half* __restrict__ A, const __half* __restrict__ Bm, void* __restrict__ Cv,
    int K, int ldc,
    const float* __restrict__ bias, const float* __restrict__ res, int ldr,
    int act, int cmode)
{
    __shared__ __half As[2][S_A];
    __shared__ __half Bs[2][S_B];
    const int tid = threadIdx.x, wid = tid >> 5, lane = tid & 31;
    const int wM = wid >> 2, wN = wid & 3;    // 2 x 4 warps; warp tile 16x32
    const int g = lane >> 2, tg = lane & 3;
    const int n0 = blockIdx.x * 128;

    float acc[4][4];
    #pragma unroll
    for (int i = 0; i < 4; i++)
        #pragma unroll
        for (int r = 0; r < 4; r++) acc[i][r] = 0.f;

    auto load_stage = [&](int buf, int k0) {
        {   // A: 32 x 64 halves
            int row = tid >> 3, col = (tid & 7) << 3;
            cp16u(As[buf] + row * 72 + col, A + (long)row * K + k0 + col);
        }
        #pragma unroll
        for (int i = 0; i < 4; i++) {  // B: 128 x 64 halves
            int c = tid + i * 256;
            int row = c >> 3, col = (c & 7) << 3;
            cp16u(Bs[buf] + row * 72 + col, Bm + (long)(n0 + row) * K + k0 + col);
        }
    };

    const int lrow = (lane & 7) + ((lane >> 3) & 1) * 8;
    const int lkof = (lane >> 4) * 8;

    auto compute = [&](int buf) {
        const uint32_t Au = (uint32_t)__cvta_generic_to_shared(As[buf]);
        const uint32_t Bu = (uint32_t)__cvta_generic_to_shared(Bs[buf]);
        #pragma unroll
        for (int ks = 0; ks < 64; ks += 16) {
            unsigned af[4], bf[4][2];
            ldsm_x4(af, Au + (uint32_t)(((wM * 16 + lrow) * 72 + ks + lkof) * 2));
            #pragma unroll
            for (int ntp = 0; ntp < 2; ntp++) {
                unsigned r[4];
                ldsm_x4(r, Bu + (uint32_t)(((wN * 32 + ntp * 16 + lrow) * 72 + ks + lkof) * 2));
                bf[2 * ntp][0] = r[0]; bf[2 * ntp + 1][0] = r[1];
                bf[2 * ntp][1] = r[2]; bf[2 * ntp + 1][1] = r[3];
            }
            #pragma unroll
            for (int nt = 0; nt < 4; nt++)
                mma_f16(acc[nt], af, bf[nt]);
        }
    };

    const int KT = K >> 6;
    load_stage(0, 0);
    cp_commit();
    for (int kt = 0; kt < KT; kt++) {
        if (kt + 1 < KT) load_stage((kt + 1) & 1, (kt + 1) * 64);
        cp_commit();
        cp_wait<1>();
        __syncthreads();
        compute(kt & 1);
        __syncthreads();
    }

    #pragma unroll
    for (int nt = 0; nt < 4; nt++) {
        int m = wM * 16 + g;
        int n = n0 + wN * 32 + nt * 8 + tg * 2;
        float bx = 0.f, by = 0.f;
        if (bias) { bx = bias[n]; by = bias[n + 1]; }
        #pragma unroll
        for (int half = 0; half < 2; half++) {
            int mm = m + half * 8;
            float2 v = make_float2(acc[nt][half * 2], acc[nt][half * 2 + 1]);
            if (bias) { v.x += bx; v.y += by; }
            if (act) {
                v.x = 0.5f * v.x * (1.f + erff(v.x * 0.70710678118654752f));
                v.y = 0.5f * v.y * (1.f + erff(v.y * 0.70710678118654752f));
            }
            if (res) {
                float2 r = *(const float2*)(res + (long)mm * ldr + n);
                v.x += r.x; v.y += r.y;
            }
            if (cmode) {
                __half2 hv = __floats2half2_rn(v.x, v.y);
                *(__half2*)((__half*)Cv + (long)mm * ldc + n) = hv;
            } else {
                *(float2*)((float*)Cv + (long)mm * ldc + n) = v;
            }
        }
    }
}

// ---------------- class attention core ----------------
__global__ void cattn_kernel(const float* __restrict__ qh, const float* __restrict__ khvh,
                             __half* __restrict__ co, const void* __restrict__ mask) {
    int z = blockIdx.x;
    int b = z / H_, h = z % H_;
    int tid = threadIdx.x;
    __shared__ float a[NTOK_];
    __shared__ float red[4];
    const float* qv = qh + (long)b * D_ + h * DH_;
    float lmax = -3.0e38f;
    for (int sidx = tid; sidx < NTOK_; sidx += 128) {
        const float* kv = khvh + ((long)(b * NTOK_ + sidx)) * KVW_ + h * DH_;
        float sc = 0.f;
        #pragma unroll
        for (int d = 0; d < DH_; d++) sc += qv[d] * kv[d];
        sc = sc * 0.125f + ((sidx == 0 || mget(mask, b * N_ + sidx - 1)) ? 0.f : -1e9f);
        a[sidx] = sc;
        lmax = fmaxf(lmax, sc);
    }
    #pragma unroll
    for (int off = 16; off; off >>= 1) lmax = fmaxf(lmax, __shfl_xor_sync(0xffffffffu, lmax, off));
    if ((tid & 31) == 0) red[tid >> 5] = lmax;
    __syncthreads();
    float m = fmaxf(fmaxf(red[0], red[1]), fmaxf(red[2], red[3]));
    __syncthreads();
    float lsum = 0.f;
    for (int sidx = tid; sidx < NTOK_; sidx += 128) {
        float e = __expf(a[sidx] - m);
        a[sidx] = e;
        lsum += e;
    }
    #pragma unroll
    for (int off = 16; off; off >>= 1) lsum += __shfl_xor_sync(0xffffffffu, lsum, off);
    if ((tid & 31) == 0) red[tid >> 5] = lsum;
    __syncthreads();
    float inv = 1.f / (red[0] + red[1] + red[2] + red[3]);
    if (tid < DH_) {
        float o = 0.f;
        for (int sidx = 0; sidx < NTOK_; sidx++)
            o += a[sidx] * khvh[((long)(b * NTOK_ + sidx)) * KVW_ + 512 + h * DH_ + tid];
        co[(long)b * D_ + h * DH_ + tid] = __float2half(o * inv);
    }
}

// ---------------- host-side launch helpers ----------------
static void launch_gemm(const __half* A, const __half* Bm, void* C,
                        int M, int Nn, int K, int lda, int ldb, int ldc,
                        const float* bias, const float* res, int ldr, int act, int cmode,
                        int nz, int zdiv,
                        long sA1, long sA2, long sB1, long sB2, long sC1, long sC2,
                        long sR1, long sR2, bool transb) {
    dim3 grid((Nn + 127) / 128, (M + 255) / 256, nz);
    bool exact = (M % 256 == 0) && (Nn % 128 == 0);
    if (transb) {
        if (exact)
            gemm_h<1,0><<<grid, 512, HSMEM_BYTES>>>(A, Bm, C, M, Nn, K, lda, ldb, ldc,
                zdiv, sA1, sA2, sB1, sB2, sC1, sC2, bias, res, ldr, sR1, sR2, act, cmode);
        else
            gemm_h<1,1><<<grid, 512, HSMEM_BYTES>>>(A, Bm, C, M, Nn, K, lda, ldb, ldc,
                zdiv, sA1, sA2, sB1, sB2, sC1, sC2, bias, res, ldr, sR1, sR2, act, cmode);
    } else {
        if (exact)
            gemm_h<0,0><<<grid, 512, HSMEM_BYTES>>>(A, Bm, C, M, Nn, K, lda, ldb, ldc,
                zdiv, sA1, sA2, sB1, sB2, sC1, sC2, bias, res, ldr, sR1, sR2, act, cmode);
        else
            gemm_h<0,1><<<grid, 512, HSMEM_BYTES>>>(A, Bm, C, M, Nn, K, lda, ldb, ldc,
                zdiv, sA1, sA2, sB1, sB2, sC1, sC2, bias, res, ldr, sR1, sR2, act, cmode);
    }
}

static void launch_gemm_simple(const __half* A, const __half* Bm, void* C,
                               int M, int Nn, int K, int lda, int ldb, int ldc,
                               const float* bias, const float* res, int ldr,
                               int act, int cmode) {
    launch_gemm(A, Bm, C, M, Nn, K, lda, ldb, ldc, bias, res, ldr, act, cmode,
                1, 1, 0, 0, 0, 0, 0, 0, 0, 0, true);
}

// M=32 class GEMM
static void launch_gemm_s(const __half* A, const __half* Bm, void* C,
                          int Nn, int K, int ldc,
                          const float* bias, const float* res, int ldr,
                          int act, int cmode) {
    gemm_s<<<Nn / 128, 256>>>(A, Bm, C, K, ldc, bias, res, ldr, act, cmode);
}

extern "C" void kernel_launch(void* const* d_in, const int* in_sizes, int n_in,
                              void* d_out, int out_size) {
    const float* x       = (const float*)d_in[0];
    const float* inter   = (const float*)d_in[1];
    const float* ctok    = (const float*)d_in[2];
    const float* p_ln1_g = (const float*)d_in[3];
    const float* p_ln1_b = (const float*)d_in[4];
    const float* p_wq    = (const float*)d_in[5];
    const float* p_wk    = (const float*)d_in[6];
    const float* p_wv    = (const float*)d_in[7];
    const float* p_wo    = (const float*)d_in[8];
    const float* p_ln2_g = (const float*)d_in[9];
    const float* p_ln2_b = (const float*)d_in[10];
    const float* p_w1    = (const float*)d_in[11];
    const float* p_b1    = (const float*)d_in[12];
    const float* p_w2    = (const float*)d_in[13];
    const float* p_b2    = (const float*)d_in[14];
    const float* c_ln1_g = (const float*)d_in[15];
    const float* c_ln1_b = (const float*)d_in[16];
    const float* c_qk    = (const float*)d_in[17];
    const float* c_qb    = (const float*)d_in[18];
    const float* c_kk    = (const float*)d_in[19];
    const float* c_kb    = (const float*)d_in[20];
    const float* c_vk    = (const float*)d_in[21];
    const float* c_vb    = (const float*)d_in[22];
    const float* c_ok    = (const float*)d_in[23];
    const float* c_ob    = (const float*)d_in[24];
    const float* c_ln2_g = (const float*)d_in[25];
    const float* c_ln2_b = (const float*)d_in[26];
    const float* c_w1    = (const float*)d_in[27];
    const float* c_b1    = (const float*)d_in[28];
    const float* c_w2    = (const float*)d_in[29];
    const float* c_b2    = (const float*)d_in[30];
    const void*  mask    = d_in[31];

    cudaFuncSetAttribute(gemm_h<0,0>, cudaFuncAttributeMaxDynamicSharedMemorySize, HSMEM_BYTES);
    cudaFuncSetAttribute(gemm_h<0,1>, cudaFuncAttributeMaxDynamicSharedMemorySize, HSMEM_BYTES);
    cudaFuncSetAttribute(gemm_h<1,0>, cudaFuncAttributeMaxDynamicSharedMemorySize, HSMEM_BYTES);
    cudaFuncSetAttribute(gemm_h<1,1>, cudaFuncAttributeMaxDynamicSharedMemorySize, HSMEM_BYTES);
    cudaFuncSetAttribute(fused_attn, cudaFuncAttributeMaxDynamicSharedMemorySize, FA_SMEM);

    float *h, *khvh, *qh, *query, *ckvb;
    __half *hn, *qkv, *ao, *interT, *t, *cn, *co, *queryh, *cfn, *cff;
    __half *wqkvT, *woT, *w1T, *w2T, *cqkT, *ckvT, *cokT, *cw1T, *cw2T;
    cudaGetSymbolAddress((void**)&h,     g_h);
    cudaGetSymbolAddress((void**)&hn,    g_hn);
    cudaGetSymbolAddress((void**)&qkv,   g_qkv);
    cudaGetSymbolAddress((void**)&ao,    g_ao);
    cudaGetSymbolAddress((void**)&interT,g_interT);
    cudaGetSymbolAddress((void**)&t,     g_t);
    cudaGetSymbolAddress((void**)&cn,    g_cn);
    cudaGetSymbolAddress((void**)&khvh,  g_khvh);
    cudaGetSymbolAddress((void**)&qh,    g_qh);
    cudaGetSymbolAddress((void**)&co,    g_co);
    cudaGetSymbolAddress((void**)&query, g_query);
    cudaGetSymbolAddress((void**)&queryh,g_queryh);
    cudaGetSymbolAddress((void**)&cfn,   g_cfn);
    cudaGetSymbolAddress((void**)&cff,   g_cff);
    cudaGetSymbolAddress((void**)&ckvb,  g_ckvb);
    cudaGetSymbolAddress((void**)&wqkvT, g_wqkvT);
    cudaGetSymbolAddress((void**)&woT,   g_woT);
    cudaGetSymbolAddress((void**)&w1T,   g_w1T);
    cudaGetSymbolAddress((void**)&w2T,   g_w2T);
    cudaGetSymbolAddress((void**)&cqkT,  g_cqkT);
    cudaGetSymbolAddress((void**)&ckvT,  g_ckvT);
    cudaGetSymbolAddress((void**)&cokT,  g_cokT);
    cudaGetSymbolAddress((void**)&cw1T,  g_cw1T);
    cudaGetSymbolAddress((void**)&cw2T,  g_cw2T);

    // ---- launch 1: ALL prep (weights + interT + ckvb + mask detect) ----
    {
        WTable w;
        auto set = [&](int i, const float* s, __half* d, int K, int N, int layers, long dStride) {
            w.src[i] = s; w.dst[i] = d; w.K[i] = K; w.N[i] = N;
            w.sS[i] = (long)K * N;
            w.dS[i] = dStride;
            int tiles = (K / 64) * (N / 64) * layers;
            w.base[i + 1] = w.base[i] + tiles;
        };
        w.base[0] = 0;
        set(0,  p_wq, wqkvT + 0L * D_,    D_, D_, L_,  (long)QKVW_ * D_);
        set(1,  p_wk, wqkvT + 512L * D_,  D_, D_, L_,  (long)QKVW_ * D_);
        set(2,  p_wv, wqkvT + 1024L * D_, D_, D_, L_,  (long)QKVW_ * D_);
        set(3,  p_wo, woT,  D_, D_, L_,  (long)D_ * D_);
        set(4,  p_w1, w1T,  D_, F_, L_,  (long)D_ * F_);
        set(5,  p_w2, w2T,  F_, D_, L_,  (long)F_ * D_);
        set(6,  c_qk, cqkT, D_, D_, LC_, (long)D_ * D_);
        set(7,  c_kk, ckvT + 0L * D_,   D_, D_, LC_, (long)KVW_ * D_);
        set(8,  c_vk, ckvT + 512L * D_, D_, D_, LC_, (long)KVW_ * D_);
        set(9,  c_ok, cokT, D_, D_, LC_, (long)D_ * D_);
        set(10, c_w1, cw1T, D_, F_, LC_, (long)D_ * F_);
        set(11, c_w2, cw2T, F_, D_, LC_, (long)D_ * F_);
        int nblk = w.base[NWT] + B_*N_ + (LC_*KVW_ + 255) / 256;
        prep_all<<<nblk, dim3(32, 8)>>>(w, inter, interT,
                                        (const unsigned int*)mask, c_kb, c_vb);
    }

    // -------- particle transformer layers --------
    for (int l = 0; l < L_; l++) {
        const float* hin = (l == 0) ? x : h;
        ln_kernel<<<B_*N_/8, 256>>>(hin, hn, p_ln1_g + (long)l * D_, p_ln1_b + (long)l * D_); // 2 (l=0)

        // fused QKV -> qkv[M, 1536] (half)        // 3 (l=0)
        launch_gemm_simple(hn, wqkvT + (long)l * QKVW_ * D_, qkv,
                           B_*N_, QKVW_, D_, D_, D_, QKVW_, nullptr, nullptr, 0, 0, 1);

        // fused score+softmax+AV -> ao (half)     // 4 (l=0) <- ncu target
        fused_attn<<<dim3(2, B_*H_), 256, FA_SMEM>>>(qkv, interT, mask, ao);

        // h = hin + ao @ Wo
        launch_gemm_simple(ao, woT + (long)l * D_ * D_, h,
                           B_*N_, D_, D_, D_, D_, D_, nullptr, hin, D_, 0, 0);

        // FFN
        ln_kernel<<<B_*N_/8, 256>>>(h, hn, p_ln2_g + (long)l * D_, p_ln2_b + (long)l * D_);
        launch_gemm_simple(hn, w1T + (long)l * F_ * D_, t,
                           B_*N_, F_, D_, D_, D_, F_, p_b1 + (long)l * F_, nullptr, 0, 1, 1);
        launch_gemm_simple(t, w2T + (long)l * D_ * F_, h,
                           B_*N_, D_, F_, F_, F_, D_, p_b2 + (long)l * D_, h, D_, 0, 0);
    }

    // -------- class attention layers --------
    bcast_token_kernel<<<(B_*D_ + 255) / 256, 256>>>(ctok);
    for (int l = 0; l < LC_; l++) {
        ln_cat_kernel<<<B_*NTOK_/8, 256>>>(query, h, cn,
                                           c_ln1_g + (long)l * D_, c_ln1_b + (long)l * D_);
        f2h_kernel<<<(B_*D_ + 255) / 256, 256>>>(query, queryh, B_*D_);
        launch_gemm_s(queryh, cqkT + (long)l * D_ * D_, qh, D_, D_, D_,
                      c_qb + (long)l * D_, nullptr, 0, 0, 0);
        launch_gemm_simple(cn, ckvT + (long)l * KVW_ * D_, khvh, B_*NTOK_, KVW_, D_,
                           D_, D_, KVW_, ckvb + (long)l * KVW_, nullptr, 0, 0, 0);

        cattn_kernel<<<B_*H_, 128>>>(qh, khvh, co, mask);

        launch_gemm_s(co, cokT + (long)l * D_ * D_, query, D_, D_, D_,
                      c_ob + (long)l * D_, query, D_, 0, 0);

        ln_small_kernel<<<(B_ + 7) / 8, 256>>>(query, cfn,
                                               c_ln2_g + (long)l * D_, c_ln2_b + (long)l * D_);
        launch_gemm_s(cfn, cw1T + (long)l * F_ * D_, cff, F_, D_, F_,
                      c_b1 + (long)l * F_, nullptr, 0, 1, 1);
        launch_gemm_s(cff, cw2T + (long)l * D_ * F_, query, D_, F_, D_,
                      c_b2 + (long)l * D_, query, D_, 0, 0);
    }

    copy_kernel<<<(B_*D_ + 255) / 256, 256>>>(query, (float*)d_out, B_*D_);
}

// round 17
// speedup vs baseline: 1.0972x; 1.0169x over previous
#include <cuda_runtime.h>
#include <cuda_fp16.h>
#include <math.h>
#include <stdint.h>

#define B_ 32
#define N_ 256
#define D_ 512
#define H_ 8
#define DH_ 64
#define F_ 2048
#define L_ 8
#define LC_ 2
#define NTOK_ 257
#define QKVW_ 1536
#define KVW_ 1024

// ---------------- scratch (device globals; no allocation allowed) ----------------
static __device__ float  g_h  [B_*N_*D_];
static __device__ __half g_hn [B_*N_*D_];
static __device__ __half g_qkv[B_*N_*QKVW_];
static __device__ __half g_ao [B_*N_*D_];
static __device__ __half g_interT[B_*H_*N_*N_];
static __device__ __half g_t  [B_*N_*F_];
static __device__ __half g_cn [B_*NTOK_*D_];
static __device__ float  g_khvh[B_*NTOK_*KVW_];
static __device__ float  g_qh [B_*D_];
static __device__ __half g_co [B_*D_];
static __device__ float  g_query[B_*D_];
static __device__ __half g_queryh[B_*D_];
static __device__ __half g_cfn[B_*D_];
static __device__ __half g_cff[B_*F_];
static __device__ float  g_ckvb[LC_*KVW_];
static __device__ int    g_mask_mode;

// transposed fp16 weights: [N][K] row-major
static __device__ __half g_wqkvT[L_*QKVW_*D_];
static __device__ __half g_woT [L_*D_*D_];
static __device__ __half g_w1T [L_*F_*D_];
static __device__ __half g_w2T [L_*D_*F_];
static __device__ __half g_cqkT[LC_*D_*D_];
static __device__ __half g_ckvT[LC_*KVW_*D_];
static __device__ __half g_cokT[LC_*D_*D_];
static __device__ __half g_cw1T[LC_*F_*D_];
static __device__ __half g_cw2T[LC_*D_*F_];

__device__ __forceinline__ bool mget(const void* m, int idx) {
    int mode = g_mask_mode;
    if (mode == 1) return ((const unsigned char*)m)[idx] != 0;
    if (mode == 2) return ((const float*)m)[idx] != 0.0f;
    return ((const int*)m)[idx] != 0;
}

// ---------------- tiny utility kernels ----------------
__global__ void copy_kernel(const float* __restrict__ src, float* __restrict__ dst, int n) {
    int i = blockIdx.x * 256 + threadIdx.x;
    if (i < n) dst[i] = src[i];
}

__global__ void f2h_kernel(const float* __restrict__ src, __half* __restrict__ dst, int n) {
    int i = blockIdx.x * 256 + threadIdx.x;
    if (i < n) dst[i] = __float2half(src[i]);
}

__global__ void bcast_token_kernel(const float* __restrict__ tok) {
    int i = blockIdx.x * 256 + threadIdx.x;
    if (i < B_*D_) g_query[i] = tok[i % D_];
}

// ---------------- ONE prep launch ----------------
#define NWT 12
struct WTable {
    const float* src[NWT];
    __half*      dst[NWT];
    int          K[NWT], N[NWT];
    long         sS[NWT], dS[NWT];
    int          base[NWT + 1];
};

__global__ void prep_all(WTable w, const float* __restrict__ inter, __half* __restrict__ interT,
                         const unsigned int* __restrict__ mask,
                         const float* __restrict__ kb, const float* __restrict__ vb) {
    int bx = blockIdx.x;
    int t = threadIdx.y * 32 + threadIdx.x;
    if (bx == 0 && t == 0) {
        unsigned int v = mask[0];
        int mode = 0;
        if (v == 0x01010101u) mode = 1;
        else if (v == 0x3F800000u) mode = 2;
        g_mask_mode = mode;
    }
    int WT = w.base[NWT];
    if (bx < WT) {
        __shared__ float tile[64][65];
        int gsel = 0;
        #pragma unroll
        for (int i = 1; i < NWT; i++) if (bx >= w.base[i]) gsel = i;
        int local = bx - w.base[gsel];
        int K = w.K[gsel], N = w.N[gsel];
        int ncols = N >> 6;
        int tpl = (K >> 6) * ncols;
        int layer = local / tpl;
        int rem = local % tpl;
        int k0 = (rem / ncols) * 64, n0 = (rem % ncols) * 64;
        const float* src = w.src[gsel] + (long)layer * w.sS[gsel];
        __half* dst = w.dst[gsel] + (long)layer * w.dS[gsel];
        #pragma unroll
        for (int i = 0; i < 4; i++) {
            int r = i * 16 + (t >> 4);
            int c = (t & 15) * 4;
            float4 v = *(const float4*)(src + (long)(k0 + r) * N + n0 + c);
            tile[r][c] = v.x; tile[r][c + 1] = v.y; tile[r][c + 2] = v.z; tile[r][c + 3] = v.w;
        }
        __syncthreads();
        #pragma unroll
        for (int i = 0; i < 8; i++) {
            int n = i * 8 + (t >> 5);
            int kc = (t & 31) * 2;
            __half2 hv = __floats2half2_rn(tile[kc][n], tile[kc + 1][n]);
            *(__half2*)(dst + (long)(n0 + n) * K + k0 + kc) = hv;
        }
    } else if (bx < WT + B_*N_) {
        int row = bx - WT;
        int b = row >> 8, qi = row & 255;
        int k = t;
        const float4* ip = (const float4*)(inter + ((long)row * N_ + k) * H_);
        float4 i0 = ip[0], i1 = ip[1];
        float v[8] = {i0.x, i0.y, i0.z, i0.w, i1.x, i1.y, i1.z, i1.w};
        #pragma unroll
        for (int h = 0; h < H_; h++)
            interT[((long)(b * H_ + h) * N_ + qi) * N_ + k] = __float2half(v[h]);
    } else {
        int i = (bx - WT - B_*N_) * 256 + t;
        if (i < LC_ * KVW_) {
            int l = i >> 10, c = i & 1023;
            g_ckvb[i] = (c < 512) ? kb[l * 512 + c] : vb[l * 512 + c - 512];
        }
    }
}

// ---------------- LayerNorm (eps = 1e-3): one WARP per row ----------------
__device__ __forceinline__ void ln_row_warp(const float* __restrict__ x, __half* __restrict__ o,
                                            const float* __restrict__ g, const float* __restrict__ bb) {
    int lane = threadIdx.x & 31;
    float4 v[4];
    #pragma unroll
    for (int i = 0; i < 4; i++)
        v[i] = *(const float4*)(x + (i * 32 + lane) * 4);
    float s = 0.f, s2 = 0.f;
    #pragma unroll
    for (int i = 0; i < 4; i++) {
        s  += v[i].x + v[i].y + v[i].z + v[i].w;
        s2 += v[i].x*v[i].x + v[i].y*v[i].y + v[i].z*v[i].z + v[i].w*v[i].w;
    }
    #pragma unroll
    for (int off = 16; off; off >>= 1) {
        s  += __shfl_xor_sync(0xffffffffu, s,  off);
        s2 += __shfl_xor_sync(0xffffffffu, s2, off);
    }
    float mean = s * (1.f / D_);
    float var  = s2 * (1.f / D_) - mean * mean;
    float r = rsqrtf(var + 1e-3f);
    #pragma unroll
    for (int i = 0; i < 4; i++) {
        int idx = (i * 32 + lane) * 4;
        float4 g4 = *(const float4*)(g + idx);
        float4 b4 = *(const float4*)(bb + idx);
        float o0 = (v[i].x - mean) * r * g4.x + b4.x;
        float o1 = (v[i].y - mean) * r * g4.y + b4.y;
        float o2 = (v[i].z - mean) * r * g4.z + b4.z;
        float o3 = (v[i].w - mean) * r * g4.w + b4.w;
        __half2 h0 = __floats2half2_rn(o0, o1);
        __half2 h1 = __floats2half2_rn(o2, o3);
        uint2 u; u.x = *(unsigned*)&h0; u.y = *(unsigned*)&h1;
        *(uint2*)(o + idx) = u;
    }
}

__global__ void ln_kernel(const float* __restrict__ in, __half* __restrict__ out,
                          const float* __restrict__ g, const float* __restrict__ b) {
    long row = blockIdx.x * 8 + (threadIdx.x >> 5);
    ln_row_warp(in + row * D_, out + row * D_, g, b);
}

__global__ void ln_cat_kernel(const float* __restrict__ query, const float* __restrict__ h,
                              __half* __restrict__ out,
                              const float* __restrict__ g, const float* __restrict__ b) {
    int row = blockIdx.x * 8 + (threadIdx.x >> 5);
    int bb = row / NTOK_, sidx = row % NTOK_;
    const float* x = (sidx == 0) ? (query + (long)bb * D_)
                                 : (h + ((long)(bb * N_) + sidx - 1) * D_);
    ln_row_warp(x, out + (long)row * D_, g, b);
}

__global__ void ln_small_kernel(const float* __restrict__ in, __half* __restrict__ out,
                                const float* __restrict__ g, const float* __restrict__ b) {
    long row = blockIdx.x * 8 + (threadIdx.x >> 5);
    if (row < B_) ln_row_warp(in + row * D_, out + row * D_, g, b);
}

// ---------------- cp.async helpers ----------------
__device__ __forceinline__ void cp16(void* smem_ptr, const void* gptr, bool pred) {
    uint32_t sa = (uint32_t)__cvta_generic_to_shared(smem_ptr);
    int sz = pred ? 16 : 0;
    asm volatile("cp.async.cg.shared.global [%0], [%1], 16, %2;\n" :: "r"(sa), "l"(gptr), "r"(sz));
}
__device__ __forceinline__ void cp16u(void* smem_ptr, const void* gptr) {
    uint32_t sa = (uint32_t)__cvta_generic_to_shared(smem_ptr);
    asm volatile("cp.async.cg.shared.global [%0], [%1], 16;\n" :: "r"(sa), "l"(gptr));
}
__device__ __forceinline__ void cp_commit() {
    asm volatile("cp.async.commit_group;\n" ::: "memory");
}
template<int NN>
__device__ __forceinline__ void cp_wait() {
    asm volatile("cp.async.wait_group %0;\n" :: "n"(NN) : "memory");
}

// ---------------- mbarrier helpers ----------------
__device__ __forceinline__ void mbar_init(uint32_t a, uint32_t cnt) {
    asm volatile("mbarrier.init.shared.b64 [%0], %1;" :: "r"(a), "r"(cnt) : "memory");
}
__device__ __forceinline__ void mbar_arrive(uint32_t a) {
    asm volatile("mbarrier.arrive.shared.b64 _, [%0];" :: "r"(a) : "memory");
}
__device__ __forceinline__ void cpasync_mbar_arrive(uint32_t a) {
    asm volatile("cp.async.mbarrier.arrive.noinc.shared.b64 [%0];" :: "r"(a) : "memory");
}
__device__ __forceinline__ void mbar_wait(uint32_t a, uint32_t parity) {
    uint32_t done = 0;
    while (!done) {
        asm volatile("{\n\t.reg .pred p;\n\t"
            "mbarrier.try_wait.parity.acquire.cta.shared::cta.b64 p, [%1], %2, 0x989680;\n\t"
            "selp.b32 %0, 1, 0, p;\n\t}" : "=r"(done) : "r"(a), "r"(parity) : "memory");
    }
}

// ---------------- ldmatrix helpers ----------------
__device__ __forceinline__ void ldsm_x4(unsigned r[4], uint32_t addr) {
    asm volatile("ldmatrix.sync.aligned.m8n8.x4.shared.b16 {%0,%1,%2,%3}, [%4];"
        : "=r"(r[0]), "=r"(r[1]), "=r"(r[2]), "=r"(r[3]) : "r"(addr));
}
__device__ __forceinline__ void ldsm_x4t(unsigned r[4], uint32_t addr) {
    asm volatile("ldmatrix.sync.aligned.m8n8.x4.trans.shared.b16 {%0,%1,%2,%3}, [%4];"
        : "=r"(r[0]), "=r"(r[1]), "=r"(r[2]), "=r"(r[3]) : "r"(addr));
}

// ---------------- fp16 tensor-core mma ----------------
__device__ __forceinline__ void mma_f16(float c[4], const unsigned a[4], const unsigned b[2]) {
    asm volatile(
        "mma.sync.aligned.m16n8k16.row.col.f32.f16.f16.f32 "
        "{%0,%1,%2,%3}, {%4,%5,%6,%7}, {%8,%9}, {%0,%1,%2,%3};\n"
        : "+f"(c[0]), "+f"(c[1]), "+f"(c[2]), "+f"(c[3])
        : "r"(a[0]), "r"(a[1]), "r"(a[2]), "r"(a[3]), "r"(b[0]), "r"(b[1]));
}

__device__ __forceinline__ unsigned pk2(float a, float b) {
    __half2 x = __floats2half2_rn(a, b);
    return *(unsigned*)&x;
}

// ---------------- fused attention (inter prefetched to smem) ----------------
// smem: Q 128x72, K 256x72, V 256x72, I 128x264 (halves), kadd 256 f32, qmsk 128 f32
#define FA_I_OFF (128*72 + 2*256*72)
#define FA_SMEM ((FA_I_OFF + 128*264) * 2 + 256*4 + 128*4)

__global__ void __launch_bounds__(256, 1) fused_attn(
    const __half* __restrict__ qkv, const __half* __restrict__ interT,
    const void* __restrict__ mask, __half* __restrict__ ao)
{
    extern __shared__ __half sm[];
    __half* Qs = sm;
    __half* Ks = sm + 128*72;
    __half* Vs = sm + 128*72 + 256*72;
    __half* Is = sm + FA_I_OFF;
    float* kadd = (float*)(sm + FA_I_OFF + 128*264);
    float* qmsk = kadd + 256;

    const int q0 = blockIdx.x * 128;
    const int bh = blockIdx.y;
    const int b = bh >> 3, h = bh & 7;
    const int tid = threadIdx.x, wid = tid >> 5, lane = tid & 31;
    const int g = lane >> 2, tg = lane & 3;

    const __half* qbase = qkv + (long)b * N_ * QKVW_ + h * DH_;

    // group 0: Q/K/V tiles
    #pragma unroll
    for (int i = 0; i < 4; i++) {
        int c = tid + i * 256;
        int row = c >> 3, ch = (c & 7) * 8;
        cp16u(Qs + row * 72 + ch, qbase + (long)(q0 + row) * QKVW_ + ch);
    }
    #pragma unroll
    for (int i = 0; i < 8; i++) {
        int c = tid + i * 256;
        int row = c >> 3, ch = (c & 7) * 8;
        cp16u(Ks + row * 72 + ch, qbase + 512  + (long)row * QKVW_ + ch);
        cp16u(Vs + row * 72 + ch, qbase + 1024 + (long)row * QKVW_ + ch);
    }
    cp_commit();
    // group 1: inter tile (128 rows x 256 halves), overlaps with QK^T mma
    {
        const __half* ib = interT + ((long)bh * N_ + q0) * N_;
        #pragma unroll
        for (int i = 0; i < 16; i++) {
            int c = tid + i * 256;
            int row = c >> 5, col = (c & 31) * 8;
            cp16u(Is + row * 264 + col, ib + (long)row * N_ + col);
        }
    }
    cp_commit();
    kadd[tid] = mget(mask, b * N_ + tid) ? 0.f : -1e9f;
    if (tid < 128) qmsk[tid] = mget(mask, b * N_ + q0 + tid) ? 1.f : 0.f;
    cp_wait<1>();          // Q/K/V ready (inter may still be in flight)
    __syncthreads();

    const uint32_t Qu = (uint32_t)__cvta_generic_to_shared(Qs);
    const uint32_t Ku = (uint32_t)__cvta_generic_to_shared(Ks);
    const uint32_t Vu = (uint32_t)__cvta_generic_to_shared(Vs);
    const int lrow  = (lane & 7) + ((lane >> 3) & 1) * 8;
    const int lkof  = (lane >> 4) * 8;
    const int tkrow = (lane & 7) + (lane >> 4) * 8;
    const int tncol = ((lane >> 3) & 1) * 8;

    float sacc[32][4];
    #pragma unroll
    for (int nt = 0; nt < 32; nt++)
        #pragma unroll
        for (int r = 0; r < 4; r++) sacc[nt][r] = 0.f;

    #pragma unroll
    for (int kt = 0; kt < 4; kt++) {
        unsigned af[4];
        ldsm_x4(af, Qu + (uint32_t)(((wid * 16 + lrow) * 72 + kt * 16 + lkof) * 2));
        #pragma unroll
        for (int ntp = 0; ntp < 16; ntp++) {
            unsigned r[4];
            ldsm_x4(r, Ku + (uint32_t)(((ntp * 16 + lrow) * 72 + kt * 16 + lkof) * 2));
            unsigned b0[2] = {r[0], r[2]}, b1[2] = {r[1], r[3]};
            mma_f16(sacc[2 * ntp],     af, b0);
            mma_f16(sacc[2 * ntp + 1], af, b1);
        }
    }

    cp_wait<0>();          // inter tile resident
    __syncthreads();

    const __half* ig  = Is + (wid * 16 + g) * 264;
    const __half* ig8 = ig + 8 * 264;
    const bool qm0 = qmsk[wid * 16 + g]     != 0.f;
    const bool qm1 = qmsk[wid * 16 + g + 8] != 0.f;

    float mx0 = -3.0e38f, mx1 = -3.0e38f;
    #pragma unroll
    for (int nt = 0; nt < 32; nt++) {
        int col = nt * 8 + 2 * tg;
        float a0 = kadd[col], a1 = kadd[col + 1];
        float2 i0 = __half22float2(*(const __half2*)(ig  + col));
        float2 i1 = __half22float2(*(const __half2*)(ig8 + col));
        float v0 = fmaf(sacc[nt][0], 0.125f, i0.x) + (qm0 ? a0 : -1e9f);
        float v1 = fmaf(sacc[nt][1], 0.125f, i0.y) + (qm0 ? a1 : -1e9f);
        float v2 = fmaf(sacc[nt][2], 0.125f, i1.x) + (qm1 ? a0 : -1e9f);
        float v3 = fmaf(sacc[nt][3], 0.125f, i1.y) + (qm1 ? a1 : -1e9f);
        sacc[nt][0] = v0; sacc[nt][1] = v1; sacc[nt][2] = v2; sacc[nt][3] = v3;
        mx0 = fmaxf(mx0, fmaxf(v0, v1));
        mx1 = fmaxf(mx1, fmaxf(v2, v3));
    }
    #pragma unroll
    for (int o = 1; o <= 2; o <<= 1) {
        mx0 = fmaxf(mx0, __shfl_xor_sync(0xffffffffu, mx0, o));
        mx1 = fmaxf(mx1, __shfl_xor_sync(0xffffffffu, mx1, o));
    }
    float s0 = 0.f, s1 = 0.f;
    #pragma unroll
    for (int nt = 0; nt < 32; nt++) {
        float e0 = __expf(sacc[nt][0] - mx0), e1 = __expf(sacc[nt][1] - mx0);
        float e2 = __expf(sacc[nt][2] - mx1), e3 = __expf(sacc[nt][3] - mx1);
        sacc[nt][0] = e0; sacc[nt][1] = e1; sacc[nt][2] = e2; sacc[nt][3] = e3;
        s0 += e0 + e1; s1 += e2 + e3;
    }
    #pragma unroll
    for (int o = 1; o <= 2; o <<= 1) {
        s0 += __shfl_xor_sync(0xffffffffu, s0, o);
        s1 += __shfl_xor_sync(0xffffffffu, s1, o);
    }

    float oacc[8][4];
    #pragma unroll
    for (int nt = 0; nt < 8; nt++)
        #pragma unroll
        for (int r = 0; r < 4; r++) oacc[nt][r] = 0.f;

    #pragma unroll
    for (int kt = 0; kt < 16; kt++) {
        unsigned ph[4];
        ph[0] = pk2(sacc[2 * kt][0],     sacc[2 * kt][1]);
        ph[1] = pk2(sacc[2 * kt][2],     sacc[2 * kt][3]);
        ph[2] = pk2(sacc[2 * kt + 1][0], sacc[2 * kt + 1][1]);
        ph[3] = pk2(sacc[2 * kt + 1][2], sacc[2 * kt + 1][3]);
        #pragma unroll
        for (int ntp = 0; ntp < 4; ntp++) {
            unsigned r[4];
            ldsm_x4t(r, Vu + (uint32_t)(((kt * 16 + tkrow) * 72 + ntp * 16 + tncol) * 2));
            unsigned b0[2] = {r[0], r[2]}, b1[2] = {r[1], r[3]};
            mma_f16(oacc[2 * ntp],     ph, b0);
            mma_f16(oacc[2 * ntp + 1], ph, b1);
        }
    }

    float inv0 = 1.f / s0, inv1 = 1.f / s1;
    const int qrow = q0 + wid * 16 + g;
    __half* aob = ao + ((long)b * N_ + qrow) * D_ + h * DH_;
    #pragma unroll
    for (int nt = 0; nt < 8; nt++) {
        int col = nt * 8 + 2 * tg;
        __half2 v0 = __floats2half2_rn(oacc[nt][0] * inv0, oacc[nt][1] * inv0);
        __half2 v1 = __floats2half2_rn(oacc[nt][2] * inv1, oacc[nt][3] * inv1);
        *(__half2*)(aob + col) = v0;
        *(__half2*)(aob + 8L * D_ + col) = v1;
    }
}

// ---------------- fp16 GEMM: BM=256 BN=128 BK=64, 512 thr, 4-stage mbarrier ring ----------------
#define GSTG 4
#define A_ST 18432
#define B_ST 9216
#define AB_OFF (GSTG * A_ST)
#define HSMEM_BYTES ((GSTG * (A_ST + B_ST)) * 2)   // 221184 B

template<int TRANSB, int CHK>
__global__ void __launch_bounds__(512, 1) gemm_h(
    const __half* __restrict__ A, const __half* __restrict__ Bm, void* __restrict__ Cv,
    int M, int Nn, int K, int lda, int ldb, int ldc,
    int zdiv, long sA1, long sA2, long sB1, long sB2, long sC1, long sC2,
    const float* __restrict__ bias, const float* __restrict__ res, int ldr,
    long sR1, long sR2, int act, int cmode)
{
    extern __shared__ __half dynh[];
    __shared__ __align__(8) unsigned long long mbars[2 * GSTG];
    const uint32_t dyn_u = (uint32_t)__cvta_generic_to_shared(dynh);
    const uint32_t mb_u  = (uint32_t)__cvta_generic_to_shared(mbars);

    int z = blockIdx.z;
    long z1 = z / zdiv, z2 = z % zdiv;
    A  += z1 * sA1 + z2 * sA2;
    Bm += z1 * sB1 + z2 * sB2;
    long coff = z1 * sC1 + z2 * sC2;
    if (res) res += z1 * sR1 + z2 * sR2;

    const int tid  = threadIdx.x;
    const int wid  = tid >> 5, lane = tid & 31;
    const int wM   = wid >> 2, wN = wid & 3;
    const int g    = lane >> 2, tg = lane & 3;
    const int m0   = blockIdx.y * 256, n0 = blockIdx.x * 128;

    if (tid == 0) {
        #pragma unroll
        for (int s = 0; s < GSTG; s++) {
            mbar_init(mb_u + s * 8, 512);
            mbar_init(mb_u + 32 + s * 8, 512);
        }
    }
    __syncthreads();

    float acc[4][4][4];
    #pragma unroll
    for (int i = 0; i < 4; i++)
        #pragma unroll
        for (int j = 0; j < 4; j++)
            #pragma unroll
            for (int r = 0; r < 4; r++) acc[i][j][r] = 0.f;

    auto load_stage = [&](int buf, int k0) {
        #pragma unroll
        for (int i = 0; i < 4; i++) {
            int c = tid + i * 512;
            int row = c >> 3, col = (c & 7) << 3;
            if (CHK) {
                bool p = (m0 + row) < M;
                const __half* gp = p ? (A + (long)(m0 + row) * lda + k0 + col) : A;
                cp16(dynh + buf * A_ST + row * 72 + col, gp, p);
            } else {
                cp16u(dynh + buf * A_ST + row * 72 + col,
                      A + (long)(m0 + row) * lda + k0 + col);
            }
        }
        if (TRANSB) {
            #pragma unroll
            for (int i = 0; i < 2; i++) {
                int c = tid + i * 512;
                int row = c >> 3, col = (c & 7) << 3;
                if (CHK) {
                    bool p = (n0 + row) < Nn;
                    const __half* gp = p ? (Bm + (long)(n0 + row) * ldb + k0 + col) : Bm;
                    cp16(dynh + AB_OFF + buf * B_ST + row * 72 + col, gp, p);
                } else {
                    cp16u(dynh + AB_OFF + buf * B_ST + row * 72 + col,
                          Bm + (long)(n0 + row) * ldb + k0 + col);
                }
            }
        } else {
            #pragma unroll
            for (int i = 0; i < 2; i++) {
                int c = tid + i * 512;
                int row = c >> 4, col = (c & 15) << 3;
                if (CHK) {
                    bool p = (n0 + col) < Nn;
                    const __half* gp = p ? (Bm + (long)(k0 + row) * ldb + n0 + col) : Bm;
                    cp16(dynh + AB_OFF + buf * B_ST + row * 136 + col, gp, p);
                } else {
                    cp16u(dynh + AB_OFF + buf * B_ST + row * 136 + col,
                          Bm + (long)(k0 + row) * ldb + n0 + col);
                }
            }
        }
    };

    const int lrow = (lane & 7) + ((lane >> 3) & 1) * 8;
    const int lkof = (lane >> 4) * 8;
    const int tkrow = (lane & 7) + (lane >> 4) * 8;
    const int tncol = ((lane >> 3) & 1) * 8;

    auto compute = [&](int buf) {
        const uint32_t As = dyn_u + (uint32_t)(buf * A_ST * 2);
        const uint32_t Bs = dyn_u + (uint32_t)((AB_OFF + buf * B_ST) * 2);
        #pragma unroll
        for (int ks = 0; ks < 64; ks += 16) {
            unsigned af[4][4], bf[4][2];
            #pragma unroll
            for (int mt = 0; mt < 4; mt++)
                ldsm_x4(af[mt],
                        As + (uint32_t)(((wM * 64 + mt * 16 + lrow) * 72 + ks + lkof) * 2));
            #pragma unroll
            for (int ntp = 0; ntp < 2; ntp++) {
                unsigned r[4];
                if (TRANSB) {
                    ldsm_x4(r, Bs + (uint32_t)(((wN * 32 + ntp * 16 + lrow) * 72
                                               + ks + lkof) * 2));
                } else {
                    ldsm_x4t(r, Bs + (uint32_t)(((ks + tkrow) * 136
                                                + wN * 32 + ntp * 16 + tncol) * 2));
                }
                bf[2 * ntp][0] = r[0]; bf[2 * ntp + 1][0] = r[1];
                bf[2 * ntp][1] = r[2]; bf[2 * ntp + 1][1] = r[3];
            }
            #pragma unroll
            for (int mt = 0; mt < 4; mt++)
                #pragma unroll
                for (int nt = 0; nt < 4; nt++)
                    mma_f16(acc[mt][nt], af[mt], bf[nt]);
        }
    };

    const int KT = K >> 6;
    #pragma unroll
    for (int s = 0; s < GSTG - 1; s++) {
        load_stage(s, s * 64);
        cpasync_mbar_arrive(mb_u + s * 8);
    }
    for (int kt = 0; kt < KT; kt++) {
        int b = kt & (GSTG - 1);
        mbar_wait(mb_u + b * 8, (kt >> 2) & 1);
        compute(b);
        mbar_arrive(mb_u + 32 + b * 8);
        int pf = kt + GSTG - 1;
        if (pf < KT) {
            int pb = pf & (GSTG - 1);
            if (pf >= GSTG)
                mbar_wait(mb_u + 32 + pb * 8, ((pf >> 2) - 1) & 1);
            load_stage(pb, pf * 64);
            cpasync_mbar_arrive(mb_u + pb * 8);
        }
    }

    #pragma unroll
    for (int mt = 0; mt < 4; mt++) {
        #pragma unroll
        for (int nt = 0; nt < 4; nt++) {
            int m = m0 + wM * 64 + mt * 16 + g;
            int n = n0 + wN * 32 + nt * 8 + tg * 2;
            if (CHK && n >= Nn) continue;
            float bx = 0.f, by = 0.f;
            if (bias) { bx = bias[n]; by = bias[n + 1]; }
            #pragma unroll
            for (int half = 0; half < 2; half++) {
                int mm = m + half * 8;
                if (CHK && mm >= M) continue;
                float2 v = make_float2(acc[mt][nt][half * 2], acc[mt][nt][half * 2 + 1]);
                if (bias) { v.x += bx; v.y += by; }
                if (act) {
                    v.x = 0.5f * v.x * (1.f + erff(v.x * 0.70710678118654752f));
                    v.y = 0.5f * v.y * (1.f + erff(v.y * 0.70710678118654752f));
                }
                if (res) {
                    float2 r = *(const float2*)(res + (long)mm * ldr + n);
                    v.x += r.x; v.y += r.y;
                }
                if (cmode) {
                    __half2 hv = __floats2half2_rn(v.x, v.y);
                    *(__half2*)((__half*)Cv + coff + (long)mm * ldc + n) = hv;
                } else {
                    *(float2*)((float*)Cv + coff + (long)mm * ldc + n) = v;
                }
            }
        }
    }
}

// ---------------- small-M fp16 GEMM: M<=32, BN=128, BK=64, 256 thr, 2-stage ----------------
#define S_A 2304
#define S_B 9216

__global__ void __launch_bounds__(256) gemm_s(
    const __half* __restrict__ A, const __half* __restrict__ Bm, void* __restrict__ Cv,
    int K, int ldc,
    const float* __restrict__ bias, const float* __restrict__ res, int ldr,
    int act, int cmode)
{
    __shared__ __half As[2][S_A];
    __shared__ __half Bs[2][S_B];
    const int tid = threadIdx.x, wid = tid >> 5, lane = tid & 31;
    const int wM = wid >> 2, wN = wid & 3;
    const int g = lane >> 2, tg = lane & 3;
    const int n0 = blockIdx.x * 128;

    float acc[4][4];
    #pragma unroll
    for (int i = 0; i < 4; i++)
        #pragma unroll
        for (int r = 0; r < 4; r++) acc[i][r] = 0.f;

    auto load_stage = [&](int buf, int k0) {
        {
            int row = tid >> 3, col = (tid & 7) << 3;
            cp16u(As[buf] + row * 72 + col, A + (long)row * K + k0 + col);
        }
        #pragma unroll
        for (int i = 0; i < 4; i++) {
            int c = tid + i * 256;
            int row = c >> 3, col = (c & 7) << 3;
            cp16u(Bs[buf] + row * 72 + col, Bm + (long)(n0 + row) * K + k0 + col);
        }
    };

    const int lrow = (lane & 7) + ((lane >> 3) & 1) * 8;
    const int lkof = (lane >> 4) * 8;

    auto compute = [&](int buf) {
        const uint32_t Au = (uint32_t)__cvta_generic_to_shared(As[buf]);
        const uint32_t Bu = (uint32_t)__cvta_generic_to_shared(Bs[buf]);
        #pragma unroll
        for (int ks = 0; ks < 64; ks += 16) {
            unsigned af[4], bf[4][2];
            ldsm_x4(af, Au + (uint32_t)(((wM * 16 + lrow) * 72 + ks + lkof) * 2));
            #pragma unroll
            for (int ntp = 0; ntp < 2; ntp++) {
                unsigned r[4];
                ldsm_x4(r, Bu + (uint32_t)(((wN * 32 + ntp * 16 + lrow) * 72 + ks + lkof) * 2));
                bf[2 * ntp][0] = r[0]; bf[2 * ntp + 1][0] = r[1];
                bf[2 * ntp][1] = r[2]; bf[2 * ntp + 1][1] = r[3];
            }
            #pragma unroll
            for (int nt = 0; nt < 4; nt++)
                mma_f16(acc[nt], af, bf[nt]);
        }
    };

    const int KT = K >> 6;
    load_stage(0, 0);
    cp_commit();
    for (int kt = 0; kt < KT; kt++) {
        if (kt + 1 < KT) load_stage((kt + 1) & 1, (kt + 1) * 64);
        cp_commit();
        cp_wait<1>();
        __syncthreads();
        compute(kt & 1);
        __syncthreads();
    }

    #pragma unroll
    for (int nt = 0; nt < 4; nt++) {
        int m = wM * 16 + g;
        int n = n0 + wN * 32 + nt * 8 + tg * 2;
        float bx = 0.f, by = 0.f;
        if (bias) { bx = bias[n]; by = bias[n + 1]; }
        #pragma unroll
        for (int half = 0; half < 2; half++) {
            int mm = m + half * 8;
            float2 v = make_float2(acc[nt][half * 2], acc[nt][half * 2 + 1]);
            if (bias) { v.x += bx; v.y += by; }
            if (act) {
                v.x = 0.5f * v.x * (1.f + erff(v.x * 0.70710678118654752f));
                v.y = 0.5f * v.y * (1.f + erff(v.y * 0.70710678118654752f));
            }
            if (res) {
                float2 r = *(const float2*)(res + (long)mm * ldr + n);
                v.x += r.x; v.y += r.y;
            }
            if (cmode) {
                __half2 hv = __floats2half2_rn(v.x, v.y);
                *(__half2*)((__half*)Cv + (long)mm * ldc + n) = hv;
            } else {
                *(float2*)((float*)Cv + (long)mm * ldc + n) = v;
            }
        }
    }
}

// ---------------- class attention core ----------------
__global__ void cattn_kernel(const float* __restrict__ qh, const float* __restrict__ khvh,
                             __half* __restrict__ co, const void* __restrict__ mask) {
    int z = blockIdx.x;
    int b = z / H_, h = z % H_;
    int tid = threadIdx.x;
    __shared__ float a[NTOK_];
    __shared__ float red[4];
    const float* qv = qh + (long)b * D_ + h * DH_;
    float lmax = -3.0e38f;
    for (int sidx = tid; sidx < NTOK_; sidx += 128) {
        const float* kv = khvh + ((long)(b * NTOK_ + sidx)) * KVW_ + h * DH_;
        float sc = 0.f;
        #pragma unroll
        for (int d = 0; d < DH_; d++) sc += qv[d] * kv[d];
        sc = sc * 0.125f + ((sidx == 0 || mget(mask, b * N_ + sidx - 1)) ? 0.f : -1e9f);
        a[sidx] = sc;
        lmax = fmaxf(lmax, sc);
    }
    #pragma unroll
    for (int off = 16; off; off >>= 1) lmax = fmaxf(lmax, __shfl_xor_sync(0xffffffffu, lmax, off));
    if ((tid & 31) == 0) red[tid >> 5] = lmax;
    __syncthreads();
    float m = fmaxf(fmaxf(red[0], red[1]), fmaxf(red[2], red[3]));
    __syncthreads();
    float lsum = 0.f;
    for (int sidx = tid; sidx < NTOK_; sidx += 128) {
        float e = __expf(a[sidx] - m);
        a[sidx] = e;
        lsum += e;
    }
    #pragma unroll
    for (int off = 16; off; off >>= 1) lsum += __shfl_xor_sync(0xffffffffu, lsum, off);
    if ((tid & 31) == 0) red[tid >> 5] = lsum;
    __syncthreads();
    float inv = 1.f / (red[0] + red[1] + red[2] + red[3]);
    if (tid < DH_) {
        float o = 0.f;
        for (int sidx = 0; sidx < NTOK_; sidx++)
            o += a[sidx] * khvh[((long)(b * NTOK_ + sidx)) * KVW_ + 512 + h * DH_ + tid];
        co[(long)b * D_ + h * DH_ + tid] = __float2half(o * inv);
    }
}

// ---------------- host-side launch helpers ----------------
static void launch_gemm(const __half* A, const __half* Bm, void* C,
                        int M, int Nn, int K, int lda, int ldb, int ldc,
                        const float* bias, const float* res, int ldr, int act, int cmode,
                        int nz, int zdiv,
                        long sA1, long sA2, long sB1, long sB2, long sC1, long sC2,
                        long sR1, long sR2, bool transb) {
    dim3 grid((Nn + 127) / 128, (M + 255) / 256, nz);
    bool exact = (M % 256 == 0) && (Nn % 128 == 0);
    if (transb) {
        if (exact)
            gemm_h<1,0><<<grid, 512, HSMEM_BYTES>>>(A, Bm, C, M, Nn, K, lda, ldb, ldc,
                zdiv, sA1, sA2, sB1, sB2, sC1, sC2, bias, res, ldr, sR1, sR2, act, cmode);
        else
            gemm_h<1,1><<<grid, 512, HSMEM_BYTES>>>(A, Bm, C, M, Nn, K, lda, ldb, ldc,
                zdiv, sA1, sA2, sB1, sB2, sC1, sC2, bias, res, ldr, sR1, sR2, act, cmode);
    } else {
        if (exact)
            gemm_h<0,0><<<grid, 512, HSMEM_BYTES>>>(A, Bm, C, M, Nn, K, lda, ldb, ldc,
                zdiv, sA1, sA2, sB1, sB2, sC1, sC2, bias, res, ldr, sR1, sR2, act, cmode);
        else
            gemm_h<0,1><<<grid, 512, HSMEM_BYTES>>>(A, Bm, C, M, Nn, K, lda, ldb, ldc,
                zdiv, sA1, sA2, sB1, sB2, sC1, sC2, bias, res, ldr, sR1, sR2, act, cmode);
    }
}

static void launch_gemm_simple(const __half* A, const __half* Bm, void* C,
                               int M, int Nn, int K, int lda, int ldb, int ldc,
                               const float* bias, const float* res, int ldr,
                               int act, int cmode) {
    launch_gemm(A, Bm, C, M, Nn, K, lda, ldb, ldc, bias, res, ldr, act, cmode,
                1, 1, 0, 0, 0, 0, 0, 0, 0, 0, true);
}

static void launch_gemm_s(const __half* A, const __half* Bm, void* C,
                          int Nn, int K, int ldc,
                          const float* bias, const float* res, int ldr,
                          int act, int cmode) {
    gemm_s<<<Nn / 128, 256>>>(A, Bm, C, K, ldc, bias, res, ldr, act, cmode);
}

extern "C" void kernel_launch(void* const* d_in, const int* in_sizes, int n_in,
                              void* d_out, int out_size) {
    const float* x       = (const float*)d_in[0];
    const float* inter   = (const float*)d_in[1];
    const float* ctok    = (const float*)d_in[2];
    const float* p_ln1_g = (const float*)d_in[3];
    const float* p_ln1_b = (const float*)d_in[4];
    const float* p_wq    = (const float*)d_in[5];
    const float* p_wk    = (const float*)d_in[6];
    const float* p_wv    = (const float*)d_in[7];
    const float* p_wo    = (const float*)d_in[8];
    const float* p_ln2_g = (const float*)d_in[9];
    const float* p_ln2_b = (const float*)d_in[10];
    const float* p_w1    = (const float*)d_in[11];
    const float* p_b1    = (const float*)d_in[12];
    const float* p_w2    = (const float*)d_in[13];
    const float* p_b2    = (const float*)d_in[14];
    const float* c_ln1_g = (const float*)d_in[15];
    const float* c_ln1_b = (const float*)d_in[16];
    const float* c_qk    = (const float*)d_in[17];
    const float* c_qb    = (const float*)d_in[18];
    const float* c_kk    = (const float*)d_in[19];
    const float* c_kb    = (const float*)d_in[20];
    const float* c_vk    = (const float*)d_in[21];
    const float* c_vb    = (const float*)d_in[22];
    const float* c_ok    = (const float*)d_in[23];
    const float* c_ob    = (const float*)d_in[24];
    const float* c_ln2_g = (const float*)d_in[25];
    const float* c_ln2_b = (const float*)d_in[26];
    const float* c_w1    = (const float*)d_in[27];
    const float* c_b1    = (const float*)d_in[28];
    const float* c_w2    = (const float*)d_in[29];
    const float* c_b2    = (const float*)d_in[30];
    const void*  mask    = d_in[31];

    cudaFuncSetAttribute(gemm_h<0,0>, cudaFuncAttributeMaxDynamicSharedMemorySize, HSMEM_BYTES);
    cudaFuncSetAttribute(gemm_h<0,1>, cudaFuncAttributeMaxDynamicSharedMemorySize, HSMEM_BYTES);
    cudaFuncSetAttribute(gemm_h<1,0>, cudaFuncAttributeMaxDynamicSharedMemorySize, HSMEM_BYTES);
    cudaFuncSetAttribute(gemm_h<1,1>, cudaFuncAttributeMaxDynamicSharedMemorySize, HSMEM_BYTES);
    cudaFuncSetAttribute(fused_attn, cudaFuncAttributeMaxDynamicSharedMemorySize, FA_SMEM);

    float *h, *khvh, *qh, *query, *ckvb;
    __half *hn, *qkv, *ao, *interT, *t, *cn, *co, *queryh, *cfn, *cff;
    __half *wqkvT, *woT, *w1T, *w2T, *cqkT, *ckvT, *cokT, *cw1T, *cw2T;
    cudaGetSymbolAddress((void**)&h,     g_h);
    cudaGetSymbolAddress((void**)&hn,    g_hn);
    cudaGetSymbolAddress((void**)&qkv,   g_qkv);
    cudaGetSymbolAddress((void**)&ao,    g_ao);
    cudaGetSymbolAddress((void**)&interT,g_interT);
    cudaGetSymbolAddress((void**)&t,     g_t);
    cudaGetSymbolAddress((void**)&cn,    g_cn);
    cudaGetSymbolAddress((void**)&khvh,  g_khvh);
    cudaGetSymbolAddress((void**)&qh,    g_qh);
    cudaGetSymbolAddress((void**)&co,    g_co);
    cudaGetSymbolAddress((void**)&query, g_query);
    cudaGetSymbolAddress((void**)&queryh,g_queryh);
    cudaGetSymbolAddress((void**)&cfn,   g_cfn);
    cudaGetSymbolAddress((void**)&cff,   g_cff);
    cudaGetSymbolAddress((void**)&ckvb,  g_ckvb);
    cudaGetSymbolAddress((void**)&wqkvT, g_wqkvT);
    cudaGetSymbolAddress((void**)&woT,   g_woT);
    cudaGetSymbolAddress((void**)&w1T,   g_w1T);
    cudaGetSymbolAddress((void**)&w2T,   g_w2T);
    cudaGetSymbolAddress((void**)&cqkT,  g_cqkT);
    cudaGetSymbolAddress((void**)&ckvT,  g_ckvT);
    cudaGetSymbolAddress((void**)&cokT,  g_cokT);
    cudaGetSymbolAddress((void**)&cw1T,  g_cw1T);
    cudaGetSymbolAddress((void**)&cw2T,  g_cw2T);

    // ---- launch 1: ALL prep ----
    {
        WTable w;
        auto set = [&](int i, const float* s, __half* d, int K, int N, int layers, long dStride) {
            w.src[i] = s; w.dst[i] = d; w.K[i] = K; w.N[i] = N;
            w.sS[i] = (long)K * N;
            w.dS[i] = dStride;
            int tiles = (K / 64) * (N / 64) * layers;
            w.base[i + 1] = w.base[i] + tiles;
        };
        w.base[0] = 0;
        set(0,  p_wq, wqkvT + 0L * D_,    D_, D_, L_,  (long)QKVW_ * D_);
        set(1,  p_wk, wqkvT + 512L * D_,  D_, D_, L_,  (long)QKVW_ * D_);
        set(2,  p_wv, wqkvT + 1024L * D_, D_, D_, L_,  (long)QKVW_ * D_);
        set(3,  p_wo, woT,  D_, D_, L_,  (long)D_ * D_);
        set(4,  p_w1, w1T,  D_, F_, L_,  (long)D_ * F_);
        set(5,  p_w2, w2T,  F_, D_, L_,  (long)F_ * D_);
        set(6,  c_qk, cqkT, D_, D_, LC_, (long)D_ * D_);
        set(7,  c_kk, ckvT + 0L * D_,   D_, D_, LC_, (long)KVW_ * D_);
        set(8,  c_vk, ckvT + 512L * D_, D_, D_, LC_, (long)KVW_ * D_);
        set(9,  c_ok, cokT, D_, D_, LC_, (long)D_ * D_);
        set(10, c_w1, cw1T, D_, F_, LC_, (long)D_ * F_);
        set(11, c_w2, cw2T, F_, D_, LC_, (long)D_ * F_);
        int nblk = w.base[NWT] + B_*N_ + (LC_*KVW_ + 255) / 256;
        prep_all<<<nblk, dim3(32, 8)>>>(w, inter, interT,
                                        (const unsigned int*)mask, c_kb, c_vb);
    }

    // -------- particle transformer layers --------
    for (int l = 0; l < L_; l++) {
        const float* hin = (l == 0) ? x : h;
        ln_kernel<<<B_*N_/8, 256>>>(hin, hn, p_ln1_g + (long)l * D_, p_ln1_b + (long)l * D_);

        launch_gemm_simple(hn, wqkvT + (long)l * QKVW_ * D_, qkv,
                           B_*N_, QKVW_, D_, D_, D_, QKVW_, nullptr, nullptr, 0, 0, 1);

        fused_attn<<<dim3(2, B_*H_), 256, FA_SMEM>>>(qkv, interT, mask, ao);

        launch_gemm_simple(ao, woT + (long)l * D_ * D_, h,
                           B_*N_, D_, D_, D_, D_, D_, nullptr, hin, D_, 0, 0);

        ln_kernel<<<B_*N_/8, 256>>>(h, hn, p_ln2_g + (long)l * D_, p_ln2_b + (long)l * D_);
        launch_gemm_simple(hn, w1T + (long)l * F_ * D_, t,
                           B_*N_, F_, D_, D_, D_, F_, p_b1 + (long)l * F_, nullptr, 0, 1, 1);
        launch_gemm_simple(t, w2T + (long)l * D_ * F_, h,
                           B_*N_, D_, F_, F_, F_, D_, p_b2 + (long)l * D_, h, D_, 0, 0);
    }

    // -------- class attention layers --------
    bcast_token_kernel<<<(B_*D_ + 255) / 256, 256>>>(ctok);
    for (int l = 0; l < LC_; l++) {
        ln_cat_kernel<<<B_*NTOK_/8, 256>>>(query, h, cn,
                                           c_ln1_g + (long)l * D_, c_ln1_b + (long)l * D_);
        f2h_kernel<<<(B_*D_ + 255) / 256, 256>>>(query, queryh, B_*D_);
        launch_gemm_s(queryh, cqkT + (long)l * D_ * D_, qh, D_, D_, D_,
                      c_qb + (long)l * D_, nullptr, 0, 0, 0);
        launch_gemm_simple(cn, ckvT + (long)l * KVW_ * D_, khvh, B_*NTOK_, KVW_, D_,
                           D_, D_, KVW_, ckvb + (long)l * KVW_, nullptr, 0, 0, 0);

        cattn_kernel<<<B_*H_, 128>>>(qh, khvh, co, mask);

        launch_gemm_s(co, cokT + (long)l * D_ * D_, query, D_, D_, D_,
                      c_ob + (long)l * D_, query, D_, 0, 0);

        ln_small_kernel<<<(B_ + 7) / 8, 256>>>(query, cfn,
                                               c_ln2_g + (long)l * D_, c_ln2_b + (long)l * D_);
        launch_gemm_s(cfn, cw1T + (long)l * F_ * D_, cff, F_, D_, F_,
                      c_b1 + (long)l * F_, nullptr, 0, 1, 1);
        launch_gemm_s(cff, cw2T + (long)l * D_ * F_, query, D_, F_, D_,
                      c_b2 + (long)l * D_, query, D_, 0, 0);
    }

    copy_kernel<<<(B_*D_ + 255) / 256, 256>>>(query, (float*)d_out, B_*D_);
}